// round 7
// baseline (speedup 1.0000x reference)
#include <cuda_runtime.h>
#include <cuda_fp16.h>
#include <stdint.h>

#define N_NODES 100000
#define N_EDGES 1600000
#define IN_CH   128
#define HID     64
#define OUT_CH  32

// gemm1 covers 3125 blocks of 32 rows; split between fusedA / fusedB
#define G1A_BLOCKS 1250
#define G1B_BLOCKS 1875
#define EDGE_BLOCKS 1563           // 1563 * 1024 edges >= N_EDGES

// ---------------- scratch (static device globals; no allocation) -------------
__device__ int     g_is64;
__device__ int     g_deg[N_NODES];
__device__ float   g_dinv[N_NODES];
__device__ int     g_rowoff[N_NODES + 1];
__device__ int     g_fill[N_NODES];
__device__ int     g_csr[N_EDGES];
__device__ int     g_partial[128];
__device__ __half2 g_t1[(size_t)N_NODES * 32];   // m1 in fp16 (64 ch)
__device__ float   g_h [(size_t)N_NODES * HID];  // post-relu hidden, fp32
__device__ __half2 g_t2[(size_t)N_NODES * 16];   // dinv * m2 in fp16 (32 ch)

// ---------------- packed fp32x2 FMA (Blackwell FFMA2) ------------------------
__device__ __forceinline__ void ffma2(float2& c, float2 a, float2 b) {
    unsigned long long A = *reinterpret_cast<unsigned long long*>(&a);
    unsigned long long B = *reinterpret_cast<unsigned long long*>(&b);
    unsigned long long C = *reinterpret_cast<unsigned long long*>(&c);
    asm("fma.rn.f32x2 %0, %1, %2, %3;" : "=l"(C) : "l"(A), "l"(B), "l"(C));
    c = *reinterpret_cast<float2*>(&C);
}

// ---------------- edge decode (dtype-agnostic) -------------------------------
__device__ __forceinline__ int load_dst(const int* __restrict__ ei, int e, int is64) {
    int d = is64 ? ei[2 * ((size_t)N_EDGES + e)] : ei[(size_t)N_EDGES + e];
    return ((unsigned)d < N_NODES) ? d : 0;
}
__device__ __forceinline__ int load_src(const int* __restrict__ ei, int e, int is64) {
    int s = is64 ? ei[2 * (size_t)e] : ei[e];
    return ((unsigned)s < N_NODES) ? s : 0;
}

// ---------------- init: zero deg + dtype sniff --------------------------------
__global__ void init_kernel(const int* __restrict__ ei32) {
    int i = blockIdx.x * blockDim.x + threadIdx.x;
    if (i < N_NODES) g_deg[i] = 0;
    if (blockIdx.x == 0 && threadIdx.x < 32) {
        int lane = threadIdx.x;
        int bad = 0;
        for (int e = lane; e < 256; e += 32)
            if (ei32[2 * e + 1] != 0) bad = 1;
        unsigned m = __ballot_sync(0xFFFFFFFFu, bad);
        if (lane == 0) g_is64 = (m == 0);
    }
}

// ---------------- GEMM1 body (writes fp16 table) ------------------------------
__device__ __forceinline__ void gemm1_body(int row0,
                                           const float* __restrict__ X,
                                           const float* __restrict__ W,
                                           float4 (*Ws)[16],
                                           float (*Xs)[IN_CH]) {
    int tid = threadIdx.x;
    const float4* W4 = (const float4*)W;
    #pragma unroll
    for (int i = tid; i < IN_CH * 16; i += 256) Ws[i >> 4][i & 15] = W4[i];

    const float4* Xg = (const float4*)(X + (size_t)row0 * IN_CH);
    float4* Xs4 = (float4*)Xs;
    #pragma unroll
    for (int i = tid; i < 32 * IN_CH / 4; i += 256) Xs4[i] = Xg[i];
    __syncthreads();

    int cg = tid & 15;
    int rs = tid >> 4;
    const float* x0p = Xs[2 * rs];
    const float* x1p = Xs[2 * rs + 1];
    float2 a0xy = {0.f, 0.f}, a0zw = {0.f, 0.f};
    float2 a1xy = {0.f, 0.f}, a1zw = {0.f, 0.f};
    #pragma unroll 4
    for (int k = 0; k < IN_CH; ++k) {
        float4 w = Ws[k][cg];
        float x0 = x0p[k], x1 = x1p[k];
        ffma2(a0xy, make_float2(w.x, w.y), make_float2(x0, x0));
        ffma2(a0zw, make_float2(w.z, w.w), make_float2(x0, x0));
        ffma2(a1xy, make_float2(w.x, w.y), make_float2(x1, x1));
        ffma2(a1zw, make_float2(w.z, w.w), make_float2(x1, x1));
    }
    // fp16 epilogue: 4 ch per row -> 2 half2 (8B) per row
    int r0 = row0 + 2 * rs;
    __half2* T = g_t1;
    T[(size_t)r0 * 32 + cg * 2]           = __floats2half2_rn(a0xy.x, a0xy.y);
    T[(size_t)r0 * 32 + cg * 2 + 1]       = __floats2half2_rn(a0zw.x, a0zw.y);
    T[(size_t)(r0 + 1) * 32 + cg * 2]     = __floats2half2_rn(a1xy.x, a1xy.y);
    T[(size_t)(r0 + 1) * 32 + cg * 2 + 1] = __floats2half2_rn(a1zw.x, a1zw.y);
}

// ---------------- fusedA: gemm1 rows [0, 40000) ⊕ degree count ---------------
__global__ void __launch_bounds__(256) fusedA_kernel(const float* __restrict__ X,
                                                     const float* __restrict__ W1,
                                                     const int* __restrict__ ei) {
    __shared__ float4 Ws[IN_CH][16];
    __shared__ float  Xs[32][IN_CH];
    int bid = blockIdx.x;
    if ((bid & 1) == 0) {
        int g = bid >> 1;
        if (g >= G1A_BLOCKS) return;
        gemm1_body(g * 32, X, W1, Ws, Xs);
    } else {
        int eb = bid >> 1;                 // < EDGE_BLOCKS
        int is64 = g_is64;
        int base = eb * 1024 + threadIdx.x;
        #pragma unroll
        for (int i = 0; i < 4; ++i) {
            int e = base + i * 256;
            if (e < N_EDGES) atomicAdd(&g_deg[load_dst(ei, e, is64)], 1);
        }
    }
}

// ---------------- fusedB: gemm1 rows [40000, 100000) ⊕ CSR fill --------------
__global__ void __launch_bounds__(256) fusedB_kernel(const float* __restrict__ X,
                                                     const float* __restrict__ W1,
                                                     const int* __restrict__ ei) {
    __shared__ float4 Ws[IN_CH][16];
    __shared__ float  Xs[32][IN_CH];
    int bid = blockIdx.x;
    if ((bid & 1) == 0) {
        int g = (bid >> 1) + G1A_BLOCKS;   // rows 40000..99999
        gemm1_body(g * 32, X, W1, Ws, Xs);
    } else {
        int eb = bid >> 1;
        if (eb >= EDGE_BLOCKS) return;
        int is64 = g_is64;
        int base = eb * 1024 + threadIdx.x;
        #pragma unroll
        for (int i = 0; i < 4; ++i) {
            int e = base + i * 256;
            if (e < N_EDGES) {
                int d = load_dst(ei, e, is64);
                int s = load_src(ei, e, is64);
                int pos = atomicAdd(&g_fill[d], 1);
                g_csr[g_rowoff[d] + pos] = s;
            }
        }
    }
}

// ---------------- exclusive scan of g_deg -> g_rowoff (+ dinv, fill=0) -------
#define SCAN_CHUNK 1024
#define SCAN_NB ((N_NODES + SCAN_CHUNK - 1) / SCAN_CHUNK)   // 98

__global__ void scan_part_kernel() {   // also computes dinv
    __shared__ int sh[256];
    int b = blockIdx.x, t = threadIdx.x;
    int base = b * SCAN_CHUNK;
    int s = 0;
    for (int i = t; i < SCAN_CHUNK; i += 256) {
        int idx = base + i;
        if (idx < N_NODES) {
            int dg = g_deg[idx];
            s += dg;
            g_dinv[idx] = rsqrtf((float)(dg + 1));   // +1 self-loop
        }
    }
    sh[t] = s; __syncthreads();
    for (int o = 128; o > 0; o >>= 1) {
        if (t < o) sh[t] += sh[t + o];
        __syncthreads();
    }
    if (t == 0) g_partial[b] = sh[0];
}

__global__ void scan_top_kernel() {   // blockDim = 128, SCAN_NB <= 128
    __shared__ int sh[128];
    int t = threadIdx.x;
    int v = (t < SCAN_NB) ? g_partial[t] : 0;
    sh[t] = v; __syncthreads();
    for (int o = 1; o < 128; o <<= 1) {
        int a = (t >= o) ? sh[t - o] : 0;
        __syncthreads();
        sh[t] += a;
        __syncthreads();
    }
    if (t < SCAN_NB) g_partial[t] = sh[t] - v;  // exclusive
}

__global__ void scan_final_kernel() {  // blockDim = 1024; also zero g_fill
    __shared__ int sh[SCAN_CHUNK];
    int b = blockIdx.x, t = threadIdx.x;
    int idx = b * SCAN_CHUNK + t;
    int v = (idx < N_NODES) ? g_deg[idx] : 0;
    sh[t] = v; __syncthreads();
    for (int o = 1; o < SCAN_CHUNK; o <<= 1) {
        int a = (t >= o) ? sh[t - o] : 0;
        __syncthreads();
        sh[t] += a;
        __syncthreads();
    }
    int incl = sh[t];
    int off = g_partial[b];
    if (idx < N_NODES) {
        g_rowoff[idx] = off + incl - v;
        g_fill[idx] = 0;
    }
    if (idx == N_NODES - 1) g_rowoff[N_NODES] = off + incl;
}

// ---------------- aggregate layer 1: warp per node, fp16 gather --------------
// h[d] = relu( di * ( sum_s dinv[s]*t1[s] + di*t1[d] ) + b1 )
__global__ void __launch_bounds__(256) aggregate1_kernel(const float* __restrict__ b1) {
    int warp = (blockIdx.x * blockDim.x + threadIdx.x) >> 5;
    if (warp >= N_NODES) return;
    int lane = threadIdx.x & 31;
    int node = warp;
    int beg = g_rowoff[node], end = g_rowoff[node + 1];
    float di = g_dinv[node];

    float2 self = __half22float2(g_t1[(size_t)node * 32 + lane]);
    float2 acc = make_float2(di * self.x, di * self.y);

    int j = beg;
    for (; j + 8 <= end; j += 8) {
        int s0 = g_csr[j],     s1 = g_csr[j + 1], s2 = g_csr[j + 2], s3 = g_csr[j + 3];
        int s4 = g_csr[j + 4], s5 = g_csr[j + 5], s6 = g_csr[j + 6], s7 = g_csr[j + 7];
        float w0 = g_dinv[s0], w1 = g_dinv[s1], w2 = g_dinv[s2], w3 = g_dinv[s3];
        float w4 = g_dinv[s4], w5 = g_dinv[s5], w6 = g_dinv[s6], w7 = g_dinv[s7];
        float2 v0 = __half22float2(g_t1[(size_t)s0 * 32 + lane]);
        float2 v1 = __half22float2(g_t1[(size_t)s1 * 32 + lane]);
        float2 v2 = __half22float2(g_t1[(size_t)s2 * 32 + lane]);
        float2 v3 = __half22float2(g_t1[(size_t)s3 * 32 + lane]);
        float2 v4 = __half22float2(g_t1[(size_t)s4 * 32 + lane]);
        float2 v5 = __half22float2(g_t1[(size_t)s5 * 32 + lane]);
        float2 v6 = __half22float2(g_t1[(size_t)s6 * 32 + lane]);
        float2 v7 = __half22float2(g_t1[(size_t)s7 * 32 + lane]);
        ffma2(acc, v0, make_float2(w0, w0));
        ffma2(acc, v1, make_float2(w1, w1));
        ffma2(acc, v2, make_float2(w2, w2));
        ffma2(acc, v3, make_float2(w3, w3));
        ffma2(acc, v4, make_float2(w4, w4));
        ffma2(acc, v5, make_float2(w5, w5));
        ffma2(acc, v6, make_float2(w6, w6));
        ffma2(acc, v7, make_float2(w7, w7));
    }
    for (; j < end; ++j) {
        int s = g_csr[j];
        float w = g_dinv[s];
        float2 v = __half22float2(g_t1[(size_t)s * 32 + lane]);
        ffma2(acc, v, make_float2(w, w));
    }
    float2 b = make_float2(b1[2 * lane], b1[2 * lane + 1]);
    ffma2(b, acc, make_float2(di, di));   // b = di*acc + bias
    float2 out;
    out.x = fmaxf(b.x, 0.f);
    out.y = fmaxf(b.y, 0.f);
    ((float2*)g_h)[(size_t)node * 32 + lane] = out;
}

// ---------------- GEMM2: t2[N,32] = dinv ⊗ (h[N,64] @ W2[64,32]), fp16 -------
__global__ void __launch_bounds__(256) gemm2_kernel(const float* __restrict__ W) {
    __shared__ float4 Ws[HID][8];        // 8 KB
    __shared__ float  Xs[64][HID];       // 16 KB
    int tid = threadIdx.x;
    const float4* W4 = (const float4*)W;
    #pragma unroll
    for (int i = tid; i < HID * 8; i += 256) Ws[i >> 3][i & 7] = W4[i];

    int row0 = blockIdx.x * 64;
    float4* Xs4 = (float4*)Xs;
    const float4* Hg = (const float4*)(g_h + (size_t)row0 * HID);
    #pragma unroll
    for (int i = tid; i < 64 * HID / 4; i += 256) {
        int row = row0 + (i >> 4);
        Xs4[i] = (row < N_NODES) ? Hg[i] : make_float4(0.f, 0.f, 0.f, 0.f);
    }
    __syncthreads();

    int cg = tid & 7;
    int rs = tid >> 3;
    const float* x0p = Xs[2 * rs];
    const float* x1p = Xs[2 * rs + 1];
    float2 a0xy = {0.f, 0.f}, a0zw = {0.f, 0.f};
    float2 a1xy = {0.f, 0.f}, a1zw = {0.f, 0.f};
    #pragma unroll 4
    for (int k = 0; k < HID; ++k) {
        float4 w = Ws[k][cg];
        float x0 = x0p[k], x1 = x1p[k];
        ffma2(a0xy, make_float2(w.x, w.y), make_float2(x0, x0));
        ffma2(a0zw, make_float2(w.z, w.w), make_float2(x0, x0));
        ffma2(a1xy, make_float2(w.x, w.y), make_float2(x1, x1));
        ffma2(a1zw, make_float2(w.z, w.w), make_float2(x1, x1));
    }
    int r0 = row0 + 2 * rs;
    if (r0 < N_NODES) {
        float d0 = g_dinv[r0];
        g_t2[(size_t)r0 * 16 + cg * 2]     = __floats2half2_rn(d0 * a0xy.x, d0 * a0xy.y);
        g_t2[(size_t)r0 * 16 + cg * 2 + 1] = __floats2half2_rn(d0 * a0zw.x, d0 * a0zw.y);
    }
    if (r0 + 1 < N_NODES) {
        float d1 = g_dinv[r0 + 1];
        g_t2[(size_t)(r0 + 1) * 16 + cg * 2]     = __floats2half2_rn(d1 * a1xy.x, d1 * a1xy.y);
        g_t2[(size_t)(r0 + 1) * 16 + cg * 2 + 1] = __floats2half2_rn(d1 * a1zw.x, d1 * a1zw.y);
    }
}

// ---------------- aggregate layer 2: warp per node, fp16 premult gather ------
// out[d] = di * ( sum_s t2[s] + t2[d] ) + b2     (t2 = dinv ⊗ m2)
__global__ void __launch_bounds__(256) aggregate2_kernel(const float* __restrict__ b2,
                                                         float* __restrict__ out) {
    int warp = (blockIdx.x * blockDim.x + threadIdx.x) >> 5;
    if (warp >= N_NODES) return;
    int lane = threadIdx.x & 31;
    int node = warp;
    int beg = g_rowoff[node], end = g_rowoff[node + 1];
    float di = g_dinv[node];
    // 16 lanes cover 32 ch as half2; half-warps split edges into even/odd slots
    int m = lane & 15;
    int eo = lane >> 4;   // 0 or 1

    float2 acc = make_float2(0.f, 0.f);
    if (eo == 0) {
        float2 self = __half22float2(g_t2[(size_t)node * 16 + m]);
        acc = self;
    }

    int j = beg;
    for (; j + 2 <= end; j += 2) {
        int s = g_csr[j + eo];
        float2 v = __half22float2(g_t2[(size_t)s * 16 + m]);
        acc.x += v.x; acc.y += v.y;
    }
    if (j < end && eo == 0) {
        int s = g_csr[j];
        float2 v = __half22float2(g_t2[(size_t)s * 16 + m]);
        acc.x += v.x; acc.y += v.y;
    }
    // combine the two edge-slot halves: lane m collects from lane m+16
    acc.x += __shfl_down_sync(0xFFFFFFFFu, acc.x, 16);
    acc.y += __shfl_down_sync(0xFFFFFFFFu, acc.y, 16);

    if (eo == 0) {
        float2 r;
        r.x = fmaf(di, acc.x, b2[2 * m]);
        r.y = fmaf(di, acc.y, b2[2 * m + 1]);
        ((float2*)out)[(size_t)node * 16 + m] = r;
    }
}

// ---------------- launch ------------------------------------------------------
extern "C" void kernel_launch(void* const* d_in, const int* in_sizes, int n_in,
                              void* d_out, int out_size) {
    const float* x  = (const float*)d_in[0];
    const int*   ei = (const int*)d_in[1];      // int32 view; dtype sniffed
    const float* W1 = (const float*)d_in[2];
    const float* b1 = (const float*)d_in[3];
    const float* W2 = (const float*)d_in[4];
    const float* b2 = (const float*)d_in[5];
    float* out = (float*)d_out;

    (void)in_sizes; (void)n_in; (void)out_size;

    init_kernel<<<(N_NODES + 255) / 256, 256>>>(ei);

    // gemm1 (part 1) overlapped with degree counting
    fusedA_kernel<<<2 * EDGE_BLOCKS, 256>>>(x, W1, ei);

    scan_part_kernel<<<SCAN_NB, 256>>>();
    scan_top_kernel<<<1, 128>>>();
    scan_final_kernel<<<SCAN_NB, SCAN_CHUNK>>>();

    // gemm1 (part 2) overlapped with CSR fill
    fusedB_kernel<<<2 * G1B_BLOCKS, 256>>>(x, W1, ei);

    aggregate1_kernel<<<(N_NODES * 32 + 255) / 256, 256>>>(b1);
    gemm2_kernel<<<(N_NODES + 63) / 64, 256>>>(W2);
    aggregate2_kernel<<<(N_NODES * 32 + 255) / 256, 256>>>(b2, out);
}

// round 8
// speedup vs baseline: 1.0764x; 1.0764x over previous
#include <cuda_runtime.h>
#include <cuda_fp16.h>
#include <stdint.h>

#define N_NODES 100000
#define N_EDGES 1600000
#define IN_CH   128
#define HID     64
#define OUT_CH  32

// gemm1 covers 3125 blocks of 32 rows; split between fusedA / fusedB
#define G1A_BLOCKS 1250
#define G1B_BLOCKS 1875
#define EDGE_BLOCKS 1563           // 1563 * 1024 edges >= N_EDGES

// ---------------- scratch (static device globals; no allocation) -------------
__device__ int     g_is64;
__device__ int     g_deg[N_NODES];
__device__ float   g_dinv[N_NODES];
__device__ int     g_rowoff[N_NODES + 1];
__device__ int     g_fill[N_NODES];
__device__ int     g_csr[N_EDGES];
__device__ int     g_partial[128];
__device__ __half2 g_t1[(size_t)N_NODES * 32];   // m1 in fp16 (64 ch)
__device__ float   g_h [(size_t)N_NODES * HID];  // post-relu hidden, fp32
__device__ __half2 g_t2[(size_t)N_NODES * 16];   // dinv * m2 in fp16 (32 ch)

// ---------------- packed fp32x2 FMA (Blackwell FFMA2) ------------------------
__device__ __forceinline__ void ffma2(float2& c, float2 a, float2 b) {
    unsigned long long A = *reinterpret_cast<unsigned long long*>(&a);
    unsigned long long B = *reinterpret_cast<unsigned long long*>(&b);
    unsigned long long C = *reinterpret_cast<unsigned long long*>(&c);
    asm("fma.rn.f32x2 %0, %1, %2, %3;" : "=l"(C) : "l"(A), "l"(B), "l"(C));
    c = *reinterpret_cast<float2*>(&C);
}

// ---------------- init: zero deg + dtype sniff --------------------------------
__global__ void init_kernel(const int* __restrict__ ei32) {
    int i = blockIdx.x * blockDim.x + threadIdx.x;
    if (i < N_NODES) g_deg[i] = 0;
    if (blockIdx.x == 0 && threadIdx.x < 32) {
        int lane = threadIdx.x;
        int bad = 0;
        for (int e = lane; e < 256; e += 32)
            if (ei32[2 * e + 1] != 0) bad = 1;
        unsigned m = __ballot_sync(0xFFFFFFFFu, bad);
        if (lane == 0) g_is64 = (m == 0);
    }
}

// ---------------- GEMM1 body (writes fp16 table) ------------------------------
__device__ __forceinline__ void gemm1_body(int row0,
                                           const float* __restrict__ X,
                                           const float* __restrict__ W,
                                           float4 (*Ws)[16],
                                           float (*Xs)[IN_CH]) {
    int tid = threadIdx.x;
    const float4* W4 = (const float4*)W;
    #pragma unroll
    for (int i = tid; i < IN_CH * 16; i += 256) Ws[i >> 4][i & 15] = W4[i];

    const float4* Xg = (const float4*)(X + (size_t)row0 * IN_CH);
    float4* Xs4 = (float4*)Xs;
    #pragma unroll
    for (int i = tid; i < 32 * IN_CH / 4; i += 256) Xs4[i] = Xg[i];
    __syncthreads();

    int cg = tid & 15;
    int rs = tid >> 4;
    const float* x0p = Xs[2 * rs];
    const float* x1p = Xs[2 * rs + 1];
    float2 a0xy = {0.f, 0.f}, a0zw = {0.f, 0.f};
    float2 a1xy = {0.f, 0.f}, a1zw = {0.f, 0.f};
    #pragma unroll 4
    for (int k = 0; k < IN_CH; ++k) {
        float4 w = Ws[k][cg];
        float x0 = x0p[k], x1 = x1p[k];
        ffma2(a0xy, make_float2(w.x, w.y), make_float2(x0, x0));
        ffma2(a0zw, make_float2(w.z, w.w), make_float2(x0, x0));
        ffma2(a1xy, make_float2(w.x, w.y), make_float2(x1, x1));
        ffma2(a1zw, make_float2(w.z, w.w), make_float2(x1, x1));
    }
    int r0 = row0 + 2 * rs;
    __half2* T = g_t1;
    T[(size_t)r0 * 32 + cg * 2]           = __floats2half2_rn(a0xy.x, a0xy.y);
    T[(size_t)r0 * 32 + cg * 2 + 1]       = __floats2half2_rn(a0zw.x, a0zw.y);
    T[(size_t)(r0 + 1) * 32 + cg * 2]     = __floats2half2_rn(a1xy.x, a1xy.y);
    T[(size_t)(r0 + 1) * 32 + cg * 2 + 1] = __floats2half2_rn(a1zw.x, a1zw.y);
}

// ---------------- fusedA: gemm1 rows [0, 40000) ⊕ degree count ---------------
__global__ void __launch_bounds__(256) fusedA_kernel(const float* __restrict__ X,
                                                     const float* __restrict__ W1,
                                                     const int* __restrict__ ei) {
    __shared__ float4 Ws[IN_CH][16];
    __shared__ float  Xs[32][IN_CH];
    int bid = blockIdx.x;
    if ((bid & 1) == 0) {
        int g = bid >> 1;
        if (g >= G1A_BLOCKS) return;
        gemm1_body(g * 32, X, W1, Ws, Xs);
    } else {
        int eb = bid >> 1;                 // < EDGE_BLOCKS
        int is64 = g_is64;
        int base = eb * 1024 + threadIdx.x;
        if (is64) {
            const int2* p = (const int2*)ei;   // dst at p[N_EDGES + e]
            #pragma unroll
            for (int i = 0; i < 4; ++i) {
                int e = base + i * 256;
                if (e < N_EDGES) {
                    int d = p[(size_t)N_EDGES + e].x;
                    if ((unsigned)d >= N_NODES) d = 0;
                    atomicAdd(&g_deg[d], 1);
                }
            }
        } else {
            #pragma unroll
            for (int i = 0; i < 4; ++i) {
                int e = base + i * 256;
                if (e < N_EDGES) {
                    int d = ei[(size_t)N_EDGES + e];
                    if ((unsigned)d >= N_NODES) d = 0;
                    atomicAdd(&g_deg[d], 1);
                }
            }
        }
    }
}

// ---------------- fusedB: gemm1 rows [40000, 100000) ⊕ CSR fill --------------
__global__ void __launch_bounds__(256) fusedB_kernel(const float* __restrict__ X,
                                                     const float* __restrict__ W1,
                                                     const int* __restrict__ ei) {
    __shared__ float4 Ws[IN_CH][16];
    __shared__ float  Xs[32][IN_CH];
    int bid = blockIdx.x;
    if ((bid & 1) == 0) {
        int g = (bid >> 1) + G1A_BLOCKS;   // rows 40000..99999
        gemm1_body(g * 32, X, W1, Ws, Xs);
    } else {
        int eb = bid >> 1;
        if (eb >= EDGE_BLOCKS) return;
        int is64 = g_is64;
        int base = eb * 1024 + threadIdx.x;
        #pragma unroll
        for (int i = 0; i < 4; ++i) {
            int e = base + i * 256;
            if (e < N_EDGES) {
                int s, d;
                if (is64) {
                    const int2* p = (const int2*)ei;
                    s = p[e].x;
                    d = p[(size_t)N_EDGES + e].x;
                } else {
                    s = ei[e];
                    d = ei[(size_t)N_EDGES + e];
                }
                if ((unsigned)s >= N_NODES) s = 0;
                if ((unsigned)d >= N_NODES) d = 0;
                int pos = atomicAdd(&g_fill[d], 1);
                g_csr[g_rowoff[d] + pos] = s;
            }
        }
    }
}

// ---------------- scan: part sums (+dinv), then final (+top scan, fill=0) ----
#define SCAN_CHUNK 1024
#define SCAN_NB ((N_NODES + SCAN_CHUNK - 1) / SCAN_CHUNK)   // 98

__global__ void scan_part_kernel() {   // also computes dinv
    __shared__ int sh[256];
    int b = blockIdx.x, t = threadIdx.x;
    int base = b * SCAN_CHUNK;
    int s = 0;
    for (int i = t; i < SCAN_CHUNK; i += 256) {
        int idx = base + i;
        if (idx < N_NODES) {
            int dg = g_deg[idx];
            s += dg;
            g_dinv[idx] = rsqrtf((float)(dg + 1));   // +1 self-loop
        }
    }
    sh[t] = s; __syncthreads();
    for (int o = 128; o > 0; o >>= 1) {
        if (t < o) sh[t] += sh[t + o];
        __syncthreads();
    }
    if (t == 0) g_partial[b] = sh[0];
}

__global__ void scan_final_kernel() {  // blockDim = 1024; fused top-scan; zero g_fill
    __shared__ int sh[SCAN_CHUNK];
    __shared__ int parts[128];
    int b = blockIdx.x, t = threadIdx.x;

    if (t < 128) parts[t] = (t < SCAN_NB) ? g_partial[t] : 0;
    __syncthreads();
    #pragma unroll
    for (int o = 1; o < 128; o <<= 1) {
        int a = (t >= o && t < 128) ? parts[t - o] : 0;
        __syncthreads();
        if (t < 128) parts[t] += a;
        __syncthreads();
    }
    int off = (b > 0) ? parts[b - 1] : 0;   // exclusive prefix of this block

    int idx = b * SCAN_CHUNK + t;
    int v = (idx < N_NODES) ? g_deg[idx] : 0;
    sh[t] = v; __syncthreads();
    #pragma unroll
    for (int o = 1; o < SCAN_CHUNK; o <<= 1) {
        int a = (t >= o) ? sh[t - o] : 0;
        __syncthreads();
        sh[t] += a;
        __syncthreads();
    }
    int incl = sh[t];
    if (idx < N_NODES) {
        g_rowoff[idx] = off + incl - v;
        g_fill[idx] = 0;
    }
    if (idx == N_NODES - 1) g_rowoff[N_NODES] = off + incl;
}

// ---------------- aggregate layer 1: HALF-warp per node ----------------------
// 16 lanes per node; each lane covers 4 channels (uint2 = 2 x half2).
// h[d] = relu( di * ( sum_s dinv[s]*t1[s] + di*t1[d] ) + b1 )
__global__ void __launch_bounds__(256) aggregate1_kernel(const float* __restrict__ b1) {
    int gw = (blockIdx.x * blockDim.x + threadIdx.x) >> 5;
    int lane = threadIdx.x & 31;
    int half = lane >> 4;          // which node of the pair
    int l = lane & 15;             // channel group within node
    int node = gw * 2 + half;
    if (node >= N_NODES) return;

    int beg = g_rowoff[node], end = g_rowoff[node + 1];
    float di = g_dinv[node];
    const uint2* T = (const uint2*)g_t1;     // 16 uint2 per node

    uint2 sr = T[(size_t)node * 16 + l];
    float2 s0 = __half22float2(*(__half2*)&sr.x);
    float2 s1 = __half22float2(*(__half2*)&sr.y);
    float2 acc0 = make_float2(di * s0.x, di * s0.y);
    float2 acc1 = make_float2(di * s1.x, di * s1.y);

    int j = beg;
    for (; j + 4 <= end; j += 4) {
        int a = g_csr[j], b_ = g_csr[j + 1], c = g_csr[j + 2], d = g_csr[j + 3];
        float wa = g_dinv[a], wb = g_dinv[b_], wc = g_dinv[c], wd = g_dinv[d];
        uint2 ra = T[(size_t)a * 16 + l];
        uint2 rb = T[(size_t)b_ * 16 + l];
        uint2 rc = T[(size_t)c * 16 + l];
        uint2 rd = T[(size_t)d * 16 + l];
        ffma2(acc0, __half22float2(*(__half2*)&ra.x), make_float2(wa, wa));
        ffma2(acc1, __half22float2(*(__half2*)&ra.y), make_float2(wa, wa));
        ffma2(acc0, __half22float2(*(__half2*)&rb.x), make_float2(wb, wb));
        ffma2(acc1, __half22float2(*(__half2*)&rb.y), make_float2(wb, wb));
        ffma2(acc0, __half22float2(*(__half2*)&rc.x), make_float2(wc, wc));
        ffma2(acc1, __half22float2(*(__half2*)&rc.y), make_float2(wc, wc));
        ffma2(acc0, __half22float2(*(__half2*)&rd.x), make_float2(wd, wd));
        ffma2(acc1, __half22float2(*(__half2*)&rd.y), make_float2(wd, wd));
    }
    for (; j < end; ++j) {
        int s = g_csr[j];
        float w = g_dinv[s];
        uint2 r = T[(size_t)s * 16 + l];
        ffma2(acc0, __half22float2(*(__half2*)&r.x), make_float2(w, w));
        ffma2(acc1, __half22float2(*(__half2*)&r.y), make_float2(w, w));
    }
    float2 bA = make_float2(b1[4 * l],     b1[4 * l + 1]);
    float2 bB = make_float2(b1[4 * l + 2], b1[4 * l + 3]);
    ffma2(bA, acc0, make_float2(di, di));
    ffma2(bB, acc1, make_float2(di, di));
    float2* H = (float2*)g_h;
    H[(size_t)node * 32 + 2 * l]     = make_float2(fmaxf(bA.x, 0.f), fmaxf(bA.y, 0.f));
    H[(size_t)node * 32 + 2 * l + 1] = make_float2(fmaxf(bB.x, 0.f), fmaxf(bB.y, 0.f));
}

// ---------------- GEMM2: t2[N,32] = dinv ⊗ (h[N,64] @ W2[64,32]), fp16 -------
__global__ void __launch_bounds__(256) gemm2_kernel(const float* __restrict__ W) {
    __shared__ float4 Ws[HID][8];        // 8 KB
    __shared__ float  Xs[64][HID];       // 16 KB
    int tid = threadIdx.x;
    const float4* W4 = (const float4*)W;
    #pragma unroll
    for (int i = tid; i < HID * 8; i += 256) Ws[i >> 3][i & 7] = W4[i];

    int row0 = blockIdx.x * 64;
    float4* Xs4 = (float4*)Xs;
    const float4* Hg = (const float4*)(g_h + (size_t)row0 * HID);
    #pragma unroll
    for (int i = tid; i < 64 * HID / 4; i += 256) {
        int row = row0 + (i >> 4);
        Xs4[i] = (row < N_NODES) ? Hg[i] : make_float4(0.f, 0.f, 0.f, 0.f);
    }
    __syncthreads();

    int cg = tid & 7;
    int rs = tid >> 3;
    const float* x0p = Xs[2 * rs];
    const float* x1p = Xs[2 * rs + 1];
    float2 a0xy = {0.f, 0.f}, a0zw = {0.f, 0.f};
    float2 a1xy = {0.f, 0.f}, a1zw = {0.f, 0.f};
    #pragma unroll 4
    for (int k = 0; k < HID; ++k) {
        float4 w = Ws[k][cg];
        float x0 = x0p[k], x1 = x1p[k];
        ffma2(a0xy, make_float2(w.x, w.y), make_float2(x0, x0));
        ffma2(a0zw, make_float2(w.z, w.w), make_float2(x0, x0));
        ffma2(a1xy, make_float2(w.x, w.y), make_float2(x1, x1));
        ffma2(a1zw, make_float2(w.z, w.w), make_float2(x1, x1));
    }
    int r0 = row0 + 2 * rs;
    if (r0 < N_NODES) {
        float d0 = g_dinv[r0];
        g_t2[(size_t)r0 * 16 + cg * 2]     = __floats2half2_rn(d0 * a0xy.x, d0 * a0xy.y);
        g_t2[(size_t)r0 * 16 + cg * 2 + 1] = __floats2half2_rn(d0 * a0zw.x, d0 * a0zw.y);
    }
    if (r0 + 1 < N_NODES) {
        float d1 = g_dinv[r0 + 1];
        g_t2[(size_t)(r0 + 1) * 16 + cg * 2]     = __floats2half2_rn(d1 * a1xy.x, d1 * a1xy.y);
        g_t2[(size_t)(r0 + 1) * 16 + cg * 2 + 1] = __floats2half2_rn(d1 * a1zw.x, d1 * a1zw.y);
    }
}

// ---------------- aggregate layer 2: warp per node, fp16 premult gather ------
// out[d] = di * ( sum_s t2[s] + t2[d] ) + b2     (t2 = dinv ⊗ m2)
__global__ void __launch_bounds__(256) aggregate2_kernel(const float* __restrict__ b2,
                                                         float* __restrict__ out) {
    int warp = (blockIdx.x * blockDim.x + threadIdx.x) >> 5;
    if (warp >= N_NODES) return;
    int lane = threadIdx.x & 31;
    int node = warp;
    int beg = g_rowoff[node], end = g_rowoff[node + 1];
    float di = g_dinv[node];
    int m = lane & 15;
    int eo = lane >> 4;   // 0 or 1: even/odd edge slot

    float2 acc = make_float2(0.f, 0.f);
    if (eo == 0) {
        acc = __half22float2(g_t2[(size_t)node * 16 + m]);
    }

    int j = beg;
    for (; j + 2 <= end; j += 2) {
        int s = g_csr[j + eo];
        float2 v = __half22float2(g_t2[(size_t)s * 16 + m]);
        acc.x += v.x; acc.y += v.y;
    }
    if (j < end && eo == 0) {
        int s = g_csr[j];
        float2 v = __half22float2(g_t2[(size_t)s * 16 + m]);
        acc.x += v.x; acc.y += v.y;
    }
    acc.x += __shfl_down_sync(0xFFFFFFFFu, acc.x, 16);
    acc.y += __shfl_down_sync(0xFFFFFFFFu, acc.y, 16);

    if (eo == 0) {
        float2 r;
        r.x = fmaf(di, acc.x, b2[2 * m]);
        r.y = fmaf(di, acc.y, b2[2 * m + 1]);
        ((float2*)out)[(size_t)node * 16 + m] = r;
    }
}

// ---------------- launch ------------------------------------------------------
extern "C" void kernel_launch(void* const* d_in, const int* in_sizes, int n_in,
                              void* d_out, int out_size) {
    const float* x  = (const float*)d_in[0];
    const int*   ei = (const int*)d_in[1];      // int32 view; dtype sniffed
    const float* W1 = (const float*)d_in[2];
    const float* b1 = (const float*)d_in[3];
    const float* W2 = (const float*)d_in[4];
    const float* b2 = (const float*)d_in[5];
    float* out = (float*)d_out;

    (void)in_sizes; (void)n_in; (void)out_size;

    init_kernel<<<(N_NODES + 255) / 256, 256>>>(ei);

    // gemm1 (part 1) overlapped with degree counting
    fusedA_kernel<<<2 * EDGE_BLOCKS, 256>>>(x, W1, ei);

    scan_part_kernel<<<SCAN_NB, 256>>>();
    scan_final_kernel<<<SCAN_NB, SCAN_CHUNK>>>();

    // gemm1 (part 2) overlapped with CSR fill
    fusedB_kernel<<<2 * G1B_BLOCKS, 256>>>(x, W1, ei);

    // half-warp per node: 50000 warps -> 6250 blocks
    aggregate1_kernel<<<(N_NODES / 2 * 32 + 255) / 256, 256>>>(b1);
    gemm2_kernel<<<(N_NODES + 63) / 64, 256>>>(W2);
    aggregate2_kernel<<<(N_NODES * 32 + 255) / 256, 256>>>(b2, out);
}

// round 9
// speedup vs baseline: 1.0898x; 1.0124x over previous
#include <cuda_runtime.h>
#include <cuda_fp16.h>
#include <stdint.h>

#define N_NODES 100000
#define N_EDGES 1600000
#define IN_CH   128
#define HID     64
#define OUT_CH  32

// gemm1 covers 3125 blocks of 32 rows; split between fusedA / fusedB
#define G1A_BLOCKS 1250
#define G1B_BLOCKS 1875
#define EDGE_BLOCKS 1563           // 1563 * 1024 edges >= N_EDGES

// ---------------- scratch (static device globals; no allocation) -------------
__device__ int     g_is64;
__device__ int     g_deg[N_NODES];
__device__ float   g_dinv[N_NODES];
__device__ int     g_rowoff[N_NODES + 1];
__device__ int     g_fill[N_NODES];
__device__ int     g_csr[N_EDGES];
__device__ int     g_partial[128];
__device__ __half2 g_t1[(size_t)N_NODES * 32];   // m1 in fp16 (64 ch)
__device__ float   g_h [(size_t)N_NODES * HID];  // post-relu hidden, fp32
__device__ __half2 g_t2[(size_t)N_NODES * 16];   // dinv * m2 in fp16 (32 ch)

// ---------------- packed fp32x2 FMA (Blackwell FFMA2) ------------------------
__device__ __forceinline__ void ffma2(float2& c, float2 a, float2 b) {
    unsigned long long A = *reinterpret_cast<unsigned long long*>(&a);
    unsigned long long B = *reinterpret_cast<unsigned long long*>(&b);
    unsigned long long C = *reinterpret_cast<unsigned long long*>(&c);
    asm("fma.rn.f32x2 %0, %1, %2, %3;" : "=l"(C) : "l"(A), "l"(B), "l"(C));
    c = *reinterpret_cast<float2*>(&C);
}
__device__ __forceinline__ float2 h2f(unsigned u) {
    return __half22float2(*(__half2*)&u);
}

// ---------------- init: zero deg + dtype sniff --------------------------------
__global__ void init_kernel(const int* __restrict__ ei32) {
    int i = blockIdx.x * blockDim.x + threadIdx.x;
    if (i < N_NODES) g_deg[i] = 0;
    if (blockIdx.x == 0 && threadIdx.x < 32) {
        int lane = threadIdx.x;
        int bad = 0;
        for (int e = lane; e < 256; e += 32)
            if (ei32[2 * e + 1] != 0) bad = 1;
        unsigned m = __ballot_sync(0xFFFFFFFFu, bad);
        if (lane == 0) g_is64 = (m == 0);
    }
}

// ---------------- GEMM1 body (writes fp16 table) ------------------------------
__device__ __forceinline__ void gemm1_body(int row0,
                                           const float* __restrict__ X,
                                           const float* __restrict__ W,
                                           float4 (*Ws)[16],
                                           float (*Xs)[IN_CH]) {
    int tid = threadIdx.x;
    const float4* W4 = (const float4*)W;
    #pragma unroll
    for (int i = tid; i < IN_CH * 16; i += 256) Ws[i >> 4][i & 15] = W4[i];

    const float4* Xg = (const float4*)(X + (size_t)row0 * IN_CH);
    float4* Xs4 = (float4*)Xs;
    #pragma unroll
    for (int i = tid; i < 32 * IN_CH / 4; i += 256) Xs4[i] = Xg[i];
    __syncthreads();

    int cg = tid & 15;
    int rs = tid >> 4;
    const float* x0p = Xs[2 * rs];
    const float* x1p = Xs[2 * rs + 1];
    float2 a0xy = {0.f, 0.f}, a0zw = {0.f, 0.f};
    float2 a1xy = {0.f, 0.f}, a1zw = {0.f, 0.f};
    #pragma unroll 4
    for (int k = 0; k < IN_CH; ++k) {
        float4 w = Ws[k][cg];
        float x0 = x0p[k], x1 = x1p[k];
        ffma2(a0xy, make_float2(w.x, w.y), make_float2(x0, x0));
        ffma2(a0zw, make_float2(w.z, w.w), make_float2(x0, x0));
        ffma2(a1xy, make_float2(w.x, w.y), make_float2(x1, x1));
        ffma2(a1zw, make_float2(w.z, w.w), make_float2(x1, x1));
    }
    int r0 = row0 + 2 * rs;
    __half2* T = g_t1;
    T[(size_t)r0 * 32 + cg * 2]           = __floats2half2_rn(a0xy.x, a0xy.y);
    T[(size_t)r0 * 32 + cg * 2 + 1]       = __floats2half2_rn(a0zw.x, a0zw.y);
    T[(size_t)(r0 + 1) * 32 + cg * 2]     = __floats2half2_rn(a1xy.x, a1xy.y);
    T[(size_t)(r0 + 1) * 32 + cg * 2 + 1] = __floats2half2_rn(a1zw.x, a1zw.y);
}

// ---------------- fusedA: gemm1 rows [0, 40000) ⊕ degree count ---------------
__global__ void __launch_bounds__(256) fusedA_kernel(const float* __restrict__ X,
                                                     const float* __restrict__ W1,
                                                     const int* __restrict__ ei) {
    __shared__ float4 Ws[IN_CH][16];
    __shared__ float  Xs[32][IN_CH];
    int bid = blockIdx.x;
    if ((bid & 1) == 0) {
        int g = bid >> 1;
        if (g >= G1A_BLOCKS) return;
        gemm1_body(g * 32, X, W1, Ws, Xs);
    } else {
        int eb = bid >> 1;                 // < EDGE_BLOCKS
        int is64 = g_is64;
        int base = eb * 1024 + threadIdx.x;
        if (is64) {
            const int2* p = (const int2*)ei;   // dst at p[N_EDGES + e]
            #pragma unroll
            for (int i = 0; i < 4; ++i) {
                int e = base + i * 256;
                if (e < N_EDGES) {
                    int d = p[(size_t)N_EDGES + e].x;
                    if ((unsigned)d >= N_NODES) d = 0;
                    atomicAdd(&g_deg[d], 1);
                }
            }
        } else {
            #pragma unroll
            for (int i = 0; i < 4; ++i) {
                int e = base + i * 256;
                if (e < N_EDGES) {
                    int d = ei[(size_t)N_EDGES + e];
                    if ((unsigned)d >= N_NODES) d = 0;
                    atomicAdd(&g_deg[d], 1);
                }
            }
        }
    }
}

// ---------------- fusedB: gemm1 rows [40000, 100000) ⊕ CSR fill --------------
__global__ void __launch_bounds__(256) fusedB_kernel(const float* __restrict__ X,
                                                     const float* __restrict__ W1,
                                                     const int* __restrict__ ei) {
    __shared__ float4 Ws[IN_CH][16];
    __shared__ float  Xs[32][IN_CH];
    int bid = blockIdx.x;
    if ((bid & 1) == 0) {
        int g = (bid >> 1) + G1A_BLOCKS;   // rows 40000..99999
        gemm1_body(g * 32, X, W1, Ws, Xs);
    } else {
        int eb = bid >> 1;
        if (eb >= EDGE_BLOCKS) return;
        int is64 = g_is64;
        int base = eb * 1024 + threadIdx.x;
        #pragma unroll
        for (int i = 0; i < 4; ++i) {
            int e = base + i * 256;
            if (e < N_EDGES) {
                int s, d;
                if (is64) {
                    const int2* p = (const int2*)ei;
                    s = p[e].x;
                    d = p[(size_t)N_EDGES + e].x;
                } else {
                    s = ei[e];
                    d = ei[(size_t)N_EDGES + e];
                }
                if ((unsigned)s >= N_NODES) s = 0;
                if ((unsigned)d >= N_NODES) d = 0;
                int pos = atomicAdd(&g_fill[d], 1);
                g_csr[g_rowoff[d] + pos] = s;
            }
        }
    }
}

// ---------------- scan: part sums (+dinv), then final (+top scan, fill=0) ----
#define SCAN_CHUNK 1024
#define SCAN_NB ((N_NODES + SCAN_CHUNK - 1) / SCAN_CHUNK)   // 98

__global__ void scan_part_kernel() {   // also computes dinv
    __shared__ int sh[256];
    int b = blockIdx.x, t = threadIdx.x;
    int base = b * SCAN_CHUNK;
    int s = 0;
    for (int i = t; i < SCAN_CHUNK; i += 256) {
        int idx = base + i;
        if (idx < N_NODES) {
            int dg = g_deg[idx];
            s += dg;
            g_dinv[idx] = rsqrtf((float)(dg + 1));   // +1 self-loop
        }
    }
    sh[t] = s; __syncthreads();
    for (int o = 128; o > 0; o >>= 1) {
        if (t < o) sh[t] += sh[t + o];
        __syncthreads();
    }
    if (t == 0) g_partial[b] = sh[0];
}

__global__ void scan_final_kernel() {  // blockDim = 1024; fused top-scan; zero g_fill
    __shared__ int sh[SCAN_CHUNK];
    __shared__ int parts[128];
    int b = blockIdx.x, t = threadIdx.x;

    if (t < 128) parts[t] = (t < SCAN_NB) ? g_partial[t] : 0;
    __syncthreads();
    #pragma unroll
    for (int o = 1; o < 128; o <<= 1) {
        int a = (t >= o && t < 128) ? parts[t - o] : 0;
        __syncthreads();
        if (t < 128) parts[t] += a;
        __syncthreads();
    }
    int off = (b > 0) ? parts[b - 1] : 0;   // exclusive prefix of this block

    int idx = b * SCAN_CHUNK + t;
    int v = (idx < N_NODES) ? g_deg[idx] : 0;
    sh[t] = v; __syncthreads();
    #pragma unroll
    for (int o = 1; o < SCAN_CHUNK; o <<= 1) {
        int a = (t >= o) ? sh[t - o] : 0;
        __syncthreads();
        sh[t] += a;
        __syncthreads();
    }
    int incl = sh[t];
    if (idx < N_NODES) {
        g_rowoff[idx] = off + incl - v;
        g_fill[idx] = 0;
    }
    if (idx == N_NODES - 1) g_rowoff[N_NODES] = off + incl;
}

// ---------------- aggregate layer 1: QUARTER-warp (8 lanes) per node ---------
// lane owns 8 channels via one uint4 (4 x half2) per gather; 128B/edge coalesced
// h[d] = relu( di * ( sum_s dinv[s]*t1[s] + di*t1[d] ) + b1 )
__global__ void __launch_bounds__(256) aggregate1_kernel(const float* __restrict__ b1) {
    int gw = (blockIdx.x * blockDim.x + threadIdx.x) >> 5;
    int lane = threadIdx.x & 31;
    int sub = lane >> 3;           // node slot within warp (0..3)
    int l = lane & 7;              // channel group (8 ch)
    int node = gw * 4 + sub;
    if (node >= N_NODES) return;

    int beg = g_rowoff[node], end = g_rowoff[node + 1];
    float di = g_dinv[node];
    const uint4* T = (const uint4*)g_t1;     // 8 uint4 per node (64 ch)

    uint4 sr = T[(size_t)node * 8 + l];
    float2 acc0 = h2f(sr.x), acc1 = h2f(sr.y), acc2 = h2f(sr.z), acc3 = h2f(sr.w);
    acc0.x *= di; acc0.y *= di; acc1.x *= di; acc1.y *= di;
    acc2.x *= di; acc2.y *= di; acc3.x *= di; acc3.y *= di;
    // second accumulator set (combined at the end)
    float2 b0 = {0.f, 0.f}, b1a = {0.f, 0.f}, b2a = {0.f, 0.f}, b3 = {0.f, 0.f};

    int j = beg;
    for (; j + 4 <= end; j += 4) {
        int sa = g_csr[j], sb = g_csr[j + 1], sc = g_csr[j + 2], sd = g_csr[j + 3];
        float wa = g_dinv[sa], wb = g_dinv[sb], wc = g_dinv[sc], wd = g_dinv[sd];
        uint4 ra = T[(size_t)sa * 8 + l];
        uint4 rb = T[(size_t)sb * 8 + l];
        uint4 rc = T[(size_t)sc * 8 + l];
        uint4 rd = T[(size_t)sd * 8 + l];
        float2 WA = make_float2(wa, wa), WB = make_float2(wb, wb);
        float2 WC = make_float2(wc, wc), WD = make_float2(wd, wd);
        ffma2(acc0, h2f(ra.x), WA); ffma2(acc1, h2f(ra.y), WA);
        ffma2(acc2, h2f(ra.z), WA); ffma2(acc3, h2f(ra.w), WA);
        ffma2(b0,   h2f(rb.x), WB); ffma2(b1a,  h2f(rb.y), WB);
        ffma2(b2a,  h2f(rb.z), WB); ffma2(b3,   h2f(rb.w), WB);
        ffma2(acc0, h2f(rc.x), WC); ffma2(acc1, h2f(rc.y), WC);
        ffma2(acc2, h2f(rc.z), WC); ffma2(acc3, h2f(rc.w), WC);
        ffma2(b0,   h2f(rd.x), WD); ffma2(b1a,  h2f(rd.y), WD);
        ffma2(b2a,  h2f(rd.z), WD); ffma2(b3,   h2f(rd.w), WD);
    }
    for (; j < end; ++j) {
        int s = g_csr[j];
        float w = g_dinv[s];
        uint4 r = T[(size_t)s * 8 + l];
        float2 W_ = make_float2(w, w);
        ffma2(acc0, h2f(r.x), W_); ffma2(acc1, h2f(r.y), W_);
        ffma2(acc2, h2f(r.z), W_); ffma2(acc3, h2f(r.w), W_);
    }
    acc0.x += b0.x;  acc0.y += b0.y;
    acc1.x += b1a.x; acc1.y += b1a.y;
    acc2.x += b2a.x; acc2.y += b2a.y;
    acc3.x += b3.x;  acc3.y += b3.y;

    const float2* B = (const float2*)b1;   // channels 8l..8l+7 = B[4l..4l+3]
    float2 o0 = B[4 * l], o1 = B[4 * l + 1], o2 = B[4 * l + 2], o3 = B[4 * l + 3];
    float2 D = make_float2(di, di);
    ffma2(o0, acc0, D); ffma2(o1, acc1, D); ffma2(o2, acc2, D); ffma2(o3, acc3, D);
    float4* H = (float4*)g_h;              // 16 float4 per node
    H[(size_t)node * 16 + 2 * l]     = make_float4(fmaxf(o0.x, 0.f), fmaxf(o0.y, 0.f),
                                                   fmaxf(o1.x, 0.f), fmaxf(o1.y, 0.f));
    H[(size_t)node * 16 + 2 * l + 1] = make_float4(fmaxf(o2.x, 0.f), fmaxf(o2.y, 0.f),
                                                   fmaxf(o3.x, 0.f), fmaxf(o3.y, 0.f));
}

// ---------------- GEMM2: t2[N,32] = dinv ⊗ (h[N,64] @ W2[64,32]), fp16 -------
__global__ void __launch_bounds__(256) gemm2_kernel(const float* __restrict__ W) {
    __shared__ float4 Ws[HID][8];        // 8 KB
    __shared__ float  Xs[64][HID];       // 16 KB
    int tid = threadIdx.x;
    const float4* W4 = (const float4*)W;
    #pragma unroll
    for (int i = tid; i < HID * 8; i += 256) Ws[i >> 3][i & 7] = W4[i];

    int row0 = blockIdx.x * 64;
    float4* Xs4 = (float4*)Xs;
    const float4* Hg = (const float4*)(g_h + (size_t)row0 * HID);
    #pragma unroll
    for (int i = tid; i < 64 * HID / 4; i += 256) {
        int row = row0 + (i >> 4);
        Xs4[i] = (row < N_NODES) ? Hg[i] : make_float4(0.f, 0.f, 0.f, 0.f);
    }
    __syncthreads();

    int cg = tid & 7;
    int rs = tid >> 3;
    const float* x0p = Xs[2 * rs];
    const float* x1p = Xs[2 * rs + 1];
    float2 a0xy = {0.f, 0.f}, a0zw = {0.f, 0.f};
    float2 a1xy = {0.f, 0.f}, a1zw = {0.f, 0.f};
    #pragma unroll 4
    for (int k = 0; k < HID; ++k) {
        float4 w = Ws[k][cg];
        float x0 = x0p[k], x1 = x1p[k];
        ffma2(a0xy, make_float2(w.x, w.y), make_float2(x0, x0));
        ffma2(a0zw, make_float2(w.z, w.w), make_float2(x0, x0));
        ffma2(a1xy, make_float2(w.x, w.y), make_float2(x1, x1));
        ffma2(a1zw, make_float2(w.z, w.w), make_float2(x1, x1));
    }
    int r0 = row0 + 2 * rs;
    if (r0 < N_NODES) {
        float d0 = g_dinv[r0];
        g_t2[(size_t)r0 * 16 + cg * 2]     = __floats2half2_rn(d0 * a0xy.x, d0 * a0xy.y);
        g_t2[(size_t)r0 * 16 + cg * 2 + 1] = __floats2half2_rn(d0 * a0zw.x, d0 * a0zw.y);
    }
    if (r0 + 1 < N_NODES) {
        float d1 = g_dinv[r0 + 1];
        g_t2[(size_t)(r0 + 1) * 16 + cg * 2]     = __floats2half2_rn(d1 * a1xy.x, d1 * a1xy.y);
        g_t2[(size_t)(r0 + 1) * 16 + cg * 2 + 1] = __floats2half2_rn(d1 * a1zw.x, d1 * a1zw.y);
    }
}

// ---------------- aggregate layer 2: HALF-warp (16 lanes) per node -----------
// lane owns one half2 (2 ch); 64B/edge coalesced
// out[d] = di * ( sum_s t2[s] + t2[d] ) + b2     (t2 = dinv ⊗ m2)
__global__ void __launch_bounds__(256) aggregate2_kernel(const float* __restrict__ b2,
                                                         float* __restrict__ out) {
    int gw = (blockIdx.x * blockDim.x + threadIdx.x) >> 5;
    int lane = threadIdx.x & 31;
    int half = lane >> 4;
    int m = lane & 15;             // half2 index (2 ch)
    int node = gw * 2 + half;
    if (node >= N_NODES) return;

    int beg = g_rowoff[node], end = g_rowoff[node + 1];
    float di = g_dinv[node];

    float2 accA = __half22float2(g_t2[(size_t)node * 16 + m]);
    float2 accB = make_float2(0.f, 0.f);

    int j = beg;
    for (; j + 4 <= end; j += 4) {
        int s0 = g_csr[j], s1 = g_csr[j + 1], s2 = g_csr[j + 2], s3 = g_csr[j + 3];
        float2 v0 = __half22float2(g_t2[(size_t)s0 * 16 + m]);
        float2 v1 = __half22float2(g_t2[(size_t)s1 * 16 + m]);
        float2 v2 = __half22float2(g_t2[(size_t)s2 * 16 + m]);
        float2 v3 = __half22float2(g_t2[(size_t)s3 * 16 + m]);
        accA.x += v0.x; accA.y += v0.y;
        accB.x += v1.x; accB.y += v1.y;
        accA.x += v2.x; accA.y += v2.y;
        accB.x += v3.x; accB.y += v3.y;
    }
    for (; j < end; ++j) {
        int s = g_csr[j];
        float2 v = __half22float2(g_t2[(size_t)s * 16 + m]);
        accA.x += v.x; accA.y += v.y;
    }
    float2 r;
    r.x = fmaf(di, accA.x + accB.x, b2[2 * m]);
    r.y = fmaf(di, accA.y + accB.y, b2[2 * m + 1]);
    ((float2*)out)[(size_t)node * 16 + m] = r;
}

// ---------------- launch ------------------------------------------------------
extern "C" void kernel_launch(void* const* d_in, const int* in_sizes, int n_in,
                              void* d_out, int out_size) {
    const float* x  = (const float*)d_in[0];
    const int*   ei = (const int*)d_in[1];      // int32 view; dtype sniffed
    const float* W1 = (const float*)d_in[2];
    const float* b1 = (const float*)d_in[3];
    const float* W2 = (const float*)d_in[4];
    const float* b2 = (const float*)d_in[5];
    float* out = (float*)d_out;

    (void)in_sizes; (void)n_in; (void)out_size;

    init_kernel<<<(N_NODES + 255) / 256, 256>>>(ei);

    // gemm1 (part 1) overlapped with degree counting
    fusedA_kernel<<<2 * EDGE_BLOCKS, 256>>>(x, W1, ei);

    scan_part_kernel<<<SCAN_NB, 256>>>();
    scan_final_kernel<<<SCAN_NB, SCAN_CHUNK>>>();

    // gemm1 (part 2) overlapped with CSR fill
    fusedB_kernel<<<2 * G1B_BLOCKS, 256>>>(x, W1, ei);

    // quarter-warp per node: 25000 warps -> 3125 blocks
    aggregate1_kernel<<<(N_NODES / 4 * 32 + 255) / 256, 256>>>(b1);
    gemm2_kernel<<<(N_NODES + 63) / 64, 256>>>(W2);
    // half-warp per node: 50000 warps -> 6250 blocks
    aggregate2_kernel<<<(N_NODES / 2 * 32 + 255) / 256, 256>>>(b2, out);
}

// round 10
// speedup vs baseline: 1.2038x; 1.1047x over previous
#include <cuda_runtime.h>
#include <cuda_fp16.h>
#include <stdint.h>

#define N_NODES 100000
#define N_EDGES 1600000
#define IN_CH   128
#define HID     64
#define OUT_CH  32

#define G1A_BLOCKS 1250
#define G1B_BLOCKS 1875
#define EDGE_BLOCKS 1563           // 1563 * 1024 edges >= N_EDGES

// ---------------- scratch (static device globals; no allocation) -------------
__device__ int     g_is64;
__device__ int     g_deg[N_NODES];
__device__ float   g_dinv[N_NODES];
__device__ int     g_rowoff[N_NODES + 1];
__device__ int     g_fill[N_NODES];          // running CSR cursor (init = rowoff)
__device__ int     g_csr[N_EDGES];
__device__ int     g_partial[128];
__device__ __half2 g_t1[(size_t)N_NODES * 32];   // m1 in fp16 (64 ch)
__device__ __half2 g_t2[(size_t)N_NODES * 16];   // dinv * m2 in fp16 (32 ch)

// ---------------- packed fp32x2 FMA (Blackwell FFMA2) ------------------------
__device__ __forceinline__ void ffma2(float2& c, float2 a, float2 b) {
    unsigned long long A = *reinterpret_cast<unsigned long long*>(&a);
    unsigned long long B = *reinterpret_cast<unsigned long long*>(&b);
    unsigned long long C = *reinterpret_cast<unsigned long long*>(&c);
    asm("fma.rn.f32x2 %0, %1, %2, %3;" : "=l"(C) : "l"(A), "l"(B), "l"(C));
    c = *reinterpret_cast<float2*>(&C);
}
__device__ __forceinline__ float2 h2f(unsigned u) {
    return __half22float2(*(__half2*)&u);
}

// ---------------- init: zero deg + dtype sniff --------------------------------
__global__ void init_kernel(const int* __restrict__ ei32) {
    int i = blockIdx.x * blockDim.x + threadIdx.x;
    if (i < N_NODES) g_deg[i] = 0;
    if (blockIdx.x == 0 && threadIdx.x < 32) {
        int lane = threadIdx.x;
        int bad = 0;
        for (int e = lane; e < 256; e += 32)
            if (ei32[2 * e + 1] != 0) bad = 1;
        unsigned m = __ballot_sync(0xFFFFFFFFu, bad);
        if (lane == 0) g_is64 = (m == 0);
    }
}

// ---------------- GEMM1 body (writes fp16 table) ------------------------------
__device__ __forceinline__ void gemm1_body(int row0,
                                           const float* __restrict__ X,
                                           const float* __restrict__ W,
                                           float4 (*Ws)[16],
                                           float (*Xs)[IN_CH]) {
    int tid = threadIdx.x;
    const float4* W4 = (const float4*)W;
    #pragma unroll
    for (int i = tid; i < IN_CH * 16; i += 256) Ws[i >> 4][i & 15] = W4[i];

    const float4* Xg = (const float4*)(X + (size_t)row0 * IN_CH);
    float4* Xs4 = (float4*)Xs;
    #pragma unroll
    for (int i = tid; i < 32 * IN_CH / 4; i += 256) Xs4[i] = Xg[i];
    __syncthreads();

    int cg = tid & 15;
    int rs = tid >> 4;
    const float* x0p = Xs[2 * rs];
    const float* x1p = Xs[2 * rs + 1];
    float2 a0xy = {0.f, 0.f}, a0zw = {0.f, 0.f};
    float2 a1xy = {0.f, 0.f}, a1zw = {0.f, 0.f};
    #pragma unroll 4
    for (int k = 0; k < IN_CH; ++k) {
        float4 w = Ws[k][cg];
        float x0 = x0p[k], x1 = x1p[k];
        ffma2(a0xy, make_float2(w.x, w.y), make_float2(x0, x0));
        ffma2(a0zw, make_float2(w.z, w.w), make_float2(x0, x0));
        ffma2(a1xy, make_float2(w.x, w.y), make_float2(x1, x1));
        ffma2(a1zw, make_float2(w.z, w.w), make_float2(x1, x1));
    }
    int r0 = row0 + 2 * rs;
    __half2* T = g_t1;
    T[(size_t)r0 * 32 + cg * 2]           = __floats2half2_rn(a0xy.x, a0xy.y);
    T[(size_t)r0 * 32 + cg * 2 + 1]       = __floats2half2_rn(a0zw.x, a0zw.y);
    T[(size_t)(r0 + 1) * 32 + cg * 2]     = __floats2half2_rn(a1xy.x, a1xy.y);
    T[(size_t)(r0 + 1) * 32 + cg * 2 + 1] = __floats2half2_rn(a1zw.x, a1zw.y);
}

// ---------------- fusedA: gemm1 rows [0, 40000) ⊕ degree count ---------------
__global__ void __launch_bounds__(256) fusedA_kernel(const float* __restrict__ X,
                                                     const float* __restrict__ W1,
                                                     const int* __restrict__ ei) {
    __shared__ float4 Ws[IN_CH][16];
    __shared__ float  Xs[32][IN_CH];
    int bid = blockIdx.x;
    if ((bid & 1) == 0) {
        int g = bid >> 1;
        if (g >= G1A_BLOCKS) return;
        gemm1_body(g * 32, X, W1, Ws, Xs);
    } else {
        int eb = bid >> 1;                 // < EDGE_BLOCKS
        int is64 = g_is64;
        int base = eb * 1024 + threadIdx.x;
        if (is64) {
            const int2* p = (const int2*)ei;
            #pragma unroll
            for (int i = 0; i < 4; ++i) {
                int e = base + i * 256;
                if (e < N_EDGES) {
                    int d = p[(size_t)N_EDGES + e].x;
                    if ((unsigned)d >= N_NODES) d = 0;
                    atomicAdd(&g_deg[d], 1);
                }
            }
        } else {
            #pragma unroll
            for (int i = 0; i < 4; ++i) {
                int e = base + i * 256;
                if (e < N_EDGES) {
                    int d = ei[(size_t)N_EDGES + e];
                    if ((unsigned)d >= N_NODES) d = 0;
                    atomicAdd(&g_deg[d], 1);
                }
            }
        }
    }
}

// ---------------- fusedB: gemm1 rows [40000, 100000) ⊕ CSR fill --------------
__global__ void __launch_bounds__(256) fusedB_kernel(const float* __restrict__ X,
                                                     const float* __restrict__ W1,
                                                     const int* __restrict__ ei) {
    __shared__ float4 Ws[IN_CH][16];
    __shared__ float  Xs[32][IN_CH];
    int bid = blockIdx.x;
    if ((bid & 1) == 0) {
        int g = (bid >> 1) + G1A_BLOCKS;
        gemm1_body(g * 32, X, W1, Ws, Xs);
    } else {
        int eb = bid >> 1;
        if (eb >= EDGE_BLOCKS) return;
        int is64 = g_is64;
        int base = eb * 1024 + threadIdx.x;
        #pragma unroll
        for (int i = 0; i < 4; ++i) {
            int e = base + i * 256;
            if (e < N_EDGES) {
                int s, d;
                if (is64) {
                    const int2* p = (const int2*)ei;
                    s = p[e].x;
                    d = p[(size_t)N_EDGES + e].x;
                } else {
                    s = ei[e];
                    d = ei[(size_t)N_EDGES + e];
                }
                if ((unsigned)s >= N_NODES) s = 0;
                if ((unsigned)d >= N_NODES) d = 0;
                int pos = atomicAdd(&g_fill[d], 1);   // absolute cursor
                g_csr[pos] = s;
            }
        }
    }
}

// ---------------- scan: part sums (+dinv), then final (+top scan) ------------
#define SCAN_CHUNK 1024
#define SCAN_NB ((N_NODES + SCAN_CHUNK - 1) / SCAN_CHUNK)   // 98

__global__ void scan_part_kernel() {   // also computes dinv
    __shared__ int sh[256];
    int b = blockIdx.x, t = threadIdx.x;
    int base = b * SCAN_CHUNK;
    int s = 0;
    for (int i = t; i < SCAN_CHUNK; i += 256) {
        int idx = base + i;
        if (idx < N_NODES) {
            int dg = g_deg[idx];
            s += dg;
            g_dinv[idx] = rsqrtf((float)(dg + 1));   // +1 self-loop
        }
    }
    sh[t] = s; __syncthreads();
    for (int o = 128; o > 0; o >>= 1) {
        if (t < o) sh[t] += sh[t + o];
        __syncthreads();
    }
    if (t == 0) g_partial[b] = sh[0];
}

__global__ void scan_final_kernel() {  // blockDim = 1024; fused top scan; fill=rowoff
    __shared__ int sh[SCAN_CHUNK];
    __shared__ int parts[128];
    int b = blockIdx.x, t = threadIdx.x;

    if (t < 128) parts[t] = (t < SCAN_NB) ? g_partial[t] : 0;
    __syncthreads();
    #pragma unroll
    for (int o = 1; o < 128; o <<= 1) {
        int a = (t >= o && t < 128) ? parts[t - o] : 0;
        __syncthreads();
        if (t < 128) parts[t] += a;
        __syncthreads();
    }
    int off = (b > 0) ? parts[b - 1] : 0;

    int idx = b * SCAN_CHUNK + t;
    int v = (idx < N_NODES) ? g_deg[idx] : 0;
    sh[t] = v; __syncthreads();
    #pragma unroll
    for (int o = 1; o < SCAN_CHUNK; o <<= 1) {
        int a = (t >= o) ? sh[t - o] : 0;
        __syncthreads();
        sh[t] += a;
        __syncthreads();
    }
    int incl = sh[t];
    if (idx < N_NODES) {
        int ro = off + incl - v;
        g_rowoff[idx] = ro;
        g_fill[idx] = ro;          // running cursor starts at row offset
    }
    if (idx == N_NODES - 1) g_rowoff[N_NODES] = off + incl;
}

// ---------------- fused agg1 + gemm2 -----------------------------------------
// Block = 32 nodes, 256 threads.
// Phase A: quarter-warp (8 lanes) per node aggregates h (relu'd) into SMEM.
// Phase B: gemm2 on the 32-row SMEM tile; epilogue writes dinv ⊗ m2 to g_t2 (fp16).
#define HS_STRIDE 72   // floats per SMEM h row (16B-aligned, +8 bank shift/row)
__global__ void __launch_bounds__(256) agg1_gemm2_kernel(const float* __restrict__ b1,
                                                         const float* __restrict__ W2) {
    __shared__ float  Hs[32 * HS_STRIDE];   // 9216 B
    __shared__ float4 Ws[HID][8];           // 8 KB
    int tid = threadIdx.x;

    // preload W2 while phase A runs its first loads
    const float4* W4 = (const float4*)W2;
    #pragma unroll
    for (int i = tid; i < HID * 8; i += 256) Ws[i >> 3][i & 7] = W4[i];

    // ---- Phase A: aggregate layer 1 ----
    int warp = tid >> 5;
    int lane = tid & 31;
    int sub = lane >> 3;
    int l = lane & 7;
    int nl = warp * 4 + sub;               // node-local 0..31
    int node = blockIdx.x * 32 + nl;

    int beg = g_rowoff[node], end = g_rowoff[node + 1];
    float di = g_dinv[node];
    const uint4* T = (const uint4*)g_t1;

    uint4 sr = T[(size_t)node * 8 + l];
    float2 acc0 = h2f(sr.x), acc1 = h2f(sr.y), acc2 = h2f(sr.z), acc3 = h2f(sr.w);
    acc0.x *= di; acc0.y *= di; acc1.x *= di; acc1.y *= di;
    acc2.x *= di; acc2.y *= di; acc3.x *= di; acc3.y *= di;
    float2 b0 = {0.f, 0.f}, b1a = {0.f, 0.f}, b2a = {0.f, 0.f}, b3 = {0.f, 0.f};

    int j = beg;
    for (; j + 4 <= end; j += 4) {
        int sa = g_csr[j], sb = g_csr[j + 1], sc = g_csr[j + 2], sd = g_csr[j + 3];
        float wa = g_dinv[sa], wb = g_dinv[sb], wc = g_dinv[sc], wd = g_dinv[sd];
        uint4 ra = T[(size_t)sa * 8 + l];
        uint4 rb = T[(size_t)sb * 8 + l];
        uint4 rc = T[(size_t)sc * 8 + l];
        uint4 rd = T[(size_t)sd * 8 + l];
        float2 WA = make_float2(wa, wa), WB = make_float2(wb, wb);
        float2 WC = make_float2(wc, wc), WD = make_float2(wd, wd);
        ffma2(acc0, h2f(ra.x), WA); ffma2(acc1, h2f(ra.y), WA);
        ffma2(acc2, h2f(ra.z), WA); ffma2(acc3, h2f(ra.w), WA);
        ffma2(b0,   h2f(rb.x), WB); ffma2(b1a,  h2f(rb.y), WB);
        ffma2(b2a,  h2f(rb.z), WB); ffma2(b3,   h2f(rb.w), WB);
        ffma2(acc0, h2f(rc.x), WC); ffma2(acc1, h2f(rc.y), WC);
        ffma2(acc2, h2f(rc.z), WC); ffma2(acc3, h2f(rc.w), WC);
        ffma2(b0,   h2f(rd.x), WD); ffma2(b1a,  h2f(rd.y), WD);
        ffma2(b2a,  h2f(rd.z), WD); ffma2(b3,   h2f(rd.w), WD);
    }
    for (; j < end; ++j) {
        int s = g_csr[j];
        float w = g_dinv[s];
        uint4 r = T[(size_t)s * 8 + l];
        float2 W_ = make_float2(w, w);
        ffma2(acc0, h2f(r.x), W_); ffma2(acc1, h2f(r.y), W_);
        ffma2(acc2, h2f(r.z), W_); ffma2(acc3, h2f(r.w), W_);
    }
    acc0.x += b0.x;  acc0.y += b0.y;
    acc1.x += b1a.x; acc1.y += b1a.y;
    acc2.x += b2a.x; acc2.y += b2a.y;
    acc3.x += b3.x;  acc3.y += b3.y;

    const float2* B = (const float2*)b1;
    float2 o0 = B[4 * l], o1 = B[4 * l + 1], o2 = B[4 * l + 2], o3 = B[4 * l + 3];
    float2 D = make_float2(di, di);
    ffma2(o0, acc0, D); ffma2(o1, acc1, D); ffma2(o2, acc2, D); ffma2(o3, acc3, D);
    float4* Hrow = (float4*)(Hs + nl * HS_STRIDE);
    Hrow[2 * l]     = make_float4(fmaxf(o0.x, 0.f), fmaxf(o0.y, 0.f),
                                  fmaxf(o1.x, 0.f), fmaxf(o1.y, 0.f));
    Hrow[2 * l + 1] = make_float4(fmaxf(o2.x, 0.f), fmaxf(o2.y, 0.f),
                                  fmaxf(o3.x, 0.f), fmaxf(o3.y, 0.f));
    __syncthreads();

    // ---- Phase B: gemm2 (32 rows x 64) @ W2 (64 x 32), dinv-premult fp16 out ----
    int cg = tid & 7;                      // col group (float4 = 4 cols)
    int rs = tid >> 3;                     // row 0..31
    const float* xp = Hs + rs * HS_STRIDE;
    float2 axy = {0.f, 0.f}, azw = {0.f, 0.f};
    #pragma unroll 8
    for (int k = 0; k < HID; ++k) {
        float4 w = Ws[k][cg];
        float x = xp[k];
        ffma2(axy, make_float2(w.x, w.y), make_float2(x, x));
        ffma2(azw, make_float2(w.z, w.w), make_float2(x, x));
    }
    int row = blockIdx.x * 32 + rs;
    float dr = g_dinv[row];
    g_t2[(size_t)row * 16 + cg * 2]     = __floats2half2_rn(dr * axy.x, dr * axy.y);
    g_t2[(size_t)row * 16 + cg * 2 + 1] = __floats2half2_rn(dr * azw.x, dr * azw.y);
}

// ---------------- aggregate layer 2: HALF-warp (16 lanes) per node -----------
__global__ void __launch_bounds__(256) aggregate2_kernel(const float* __restrict__ b2,
                                                         float* __restrict__ out) {
    int gw = (blockIdx.x * blockDim.x + threadIdx.x) >> 5;
    int lane = threadIdx.x & 31;
    int half = lane >> 4;
    int m = lane & 15;
    int node = gw * 2 + half;
    if (node >= N_NODES) return;

    int beg = g_rowoff[node], end = g_rowoff[node + 1];
    float di = g_dinv[node];

    float2 accA = __half22float2(g_t2[(size_t)node * 16 + m]);
    float2 accB = make_float2(0.f, 0.f);

    int j = beg;
    for (; j + 4 <= end; j += 4) {
        int s0 = g_csr[j], s1 = g_csr[j + 1], s2 = g_csr[j + 2], s3 = g_csr[j + 3];
        float2 v0 = __half22float2(g_t2[(size_t)s0 * 16 + m]);
        float2 v1 = __half22float2(g_t2[(size_t)s1 * 16 + m]);
        float2 v2 = __half22float2(g_t2[(size_t)s2 * 16 + m]);
        float2 v3 = __half22float2(g_t2[(size_t)s3 * 16 + m]);
        accA.x += v0.x; accA.y += v0.y;
        accB.x += v1.x; accB.y += v1.y;
        accA.x += v2.x; accA.y += v2.y;
        accB.x += v3.x; accB.y += v3.y;
    }
    for (; j < end; ++j) {
        int s = g_csr[j];
        float2 v = __half22float2(g_t2[(size_t)s * 16 + m]);
        accA.x += v.x; accA.y += v.y;
    }
    float2 r;
    r.x = fmaf(di, accA.x + accB.x, b2[2 * m]);
    r.y = fmaf(di, accA.y + accB.y, b2[2 * m + 1]);
    ((float2*)out)[(size_t)node * 16 + m] = r;
}

// ---------------- launch ------------------------------------------------------
extern "C" void kernel_launch(void* const* d_in, const int* in_sizes, int n_in,
                              void* d_out, int out_size) {
    const float* x  = (const float*)d_in[0];
    const int*   ei = (const int*)d_in[1];
    const float* W1 = (const float*)d_in[2];
    const float* b1 = (const float*)d_in[3];
    const float* W2 = (const float*)d_in[4];
    const float* b2 = (const float*)d_in[5];
    float* out = (float*)d_out;

    (void)in_sizes; (void)n_in; (void)out_size;

    init_kernel<<<(N_NODES + 255) / 256, 256>>>(ei);
    fusedA_kernel<<<2 * EDGE_BLOCKS, 256>>>(x, W1, ei);
    scan_part_kernel<<<SCAN_NB, 256>>>();
    scan_final_kernel<<<SCAN_NB, SCAN_CHUNK>>>();
    fusedB_kernel<<<2 * G1B_BLOCKS, 256>>>(x, W1, ei);
    agg1_gemm2_kernel<<<N_NODES / 32, 256>>>(b1, W2);
    aggregate2_kernel<<<(N_NODES / 2 * 32 + 255) / 256, 256>>>(b2, out);
}

// round 12
// speedup vs baseline: 1.2324x; 1.0237x over previous
#include <cuda_runtime.h>
#include <cuda_fp16.h>
#include <stdint.h>

#define N_NODES 100000
#define N_EDGES 1600000
#define IN_CH   128
#define HID     64
#define OUT_CH  32

#define G1A_BLOCKS 1250
#define G1B_BLOCKS 1875
#define EDGE_BLOCKS 1563           // 1563 * 1024 edges >= N_EDGES

// ---------------- scratch (static device globals; no allocation) -------------
__device__ int     g_is64;
__device__ int     g_deg[N_NODES];
__device__ float   g_dinv[N_NODES];
__device__ int     g_rowoff[N_NODES + 1];
__device__ int     g_fill[N_NODES];          // running CSR cursor (init = rowoff)
__device__ int     g_csr[N_EDGES];
__device__ int     g_partial[128];
__device__ __half2 g_t1[(size_t)N_NODES * 32];   // m1 in fp16 (64 ch)
__device__ __half2 g_t2[(size_t)N_NODES * 16];   // dinv * m2 in fp16 (32 ch)

// ---------------- packed fp32x2 FMA (Blackwell FFMA2) ------------------------
__device__ __forceinline__ void ffma2(float2& c, float2 a, float2 b) {
    unsigned long long A = *reinterpret_cast<unsigned long long*>(&a);
    unsigned long long B = *reinterpret_cast<unsigned long long*>(&b);
    unsigned long long C = *reinterpret_cast<unsigned long long*>(&c);
    asm("fma.rn.f32x2 %0, %1, %2, %3;" : "=l"(C) : "l"(A), "l"(B), "l"(C));
    c = *reinterpret_cast<float2*>(&C);
}
__device__ __forceinline__ float2 h2f(unsigned u) {
    return __half22float2(*(__half2*)&u);
}
__device__ __forceinline__ int warp_incl_scan(int x, int lane) {
    #pragma unroll
    for (int o = 1; o < 32; o <<= 1) {
        int t = __shfl_up_sync(0xFFFFFFFFu, x, o);
        if (lane >= o) x += t;
    }
    return x;
}

// ---------------- init: zero deg + dtype sniff --------------------------------
__global__ void init_kernel(const int* __restrict__ ei32) {
    int i = blockIdx.x * blockDim.x + threadIdx.x;
    if (i < N_NODES) g_deg[i] = 0;
    if (blockIdx.x == 0 && threadIdx.x < 32) {
        int lane = threadIdx.x;
        int bad = 0;
        for (int e = lane; e < 256; e += 32)
            if (ei32[2 * e + 1] != 0) bad = 1;
        unsigned m = __ballot_sync(0xFFFFFFFFu, bad);
        if (lane == 0) g_is64 = (m == 0);
    }
}

// ---------------- GEMM1 body (writes fp16 table) ------------------------------
__device__ __forceinline__ void gemm1_body(int row0,
                                           const float* __restrict__ X,
                                           const float* __restrict__ W,
                                           float4 (*Ws)[16],
                                           float (*Xs)[IN_CH]) {
    int tid = threadIdx.x;
    const float4* W4 = (const float4*)W;
    #pragma unroll
    for (int i = tid; i < IN_CH * 16; i += 256) Ws[i >> 4][i & 15] = W4[i];

    const float4* Xg = (const float4*)(X + (size_t)row0 * IN_CH);
    float4* Xs4 = (float4*)Xs;
    #pragma unroll
    for (int i = tid; i < 32 * IN_CH / 4; i += 256) Xs4[i] = Xg[i];
    __syncthreads();

    int cg = tid & 15;
    int rs = tid >> 4;
    const float* x0p = Xs[2 * rs];
    const float* x1p = Xs[2 * rs + 1];
    float2 a0xy = {0.f, 0.f}, a0zw = {0.f, 0.f};
    float2 a1xy = {0.f, 0.f}, a1zw = {0.f, 0.f};
    #pragma unroll 4
    for (int k = 0; k < IN_CH; ++k) {
        float4 w = Ws[k][cg];
        float x0 = x0p[k], x1 = x1p[k];
        ffma2(a0xy, make_float2(w.x, w.y), make_float2(x0, x0));
        ffma2(a0zw, make_float2(w.z, w.w), make_float2(x0, x0));
        ffma2(a1xy, make_float2(w.x, w.y), make_float2(x1, x1));
        ffma2(a1zw, make_float2(w.z, w.w), make_float2(x1, x1));
    }
    int r0 = row0 + 2 * rs;
    __half2* T = g_t1;
    T[(size_t)r0 * 32 + cg * 2]           = __floats2half2_rn(a0xy.x, a0xy.y);
    T[(size_t)r0 * 32 + cg * 2 + 1]       = __floats2half2_rn(a0zw.x, a0zw.y);
    T[(size_t)(r0 + 1) * 32 + cg * 2]     = __floats2half2_rn(a1xy.x, a1xy.y);
    T[(size_t)(r0 + 1) * 32 + cg * 2 + 1] = __floats2half2_rn(a1zw.x, a1zw.y);
}

// ---------------- fusedA: gemm1 rows [0, 40000) ⊕ degree count ---------------
__global__ void __launch_bounds__(256) fusedA_kernel(const float* __restrict__ X,
                                                     const float* __restrict__ W1,
                                                     const int* __restrict__ ei) {
    __shared__ float4 Ws[IN_CH][16];
    __shared__ float  Xs[32][IN_CH];
    int bid = blockIdx.x;
    if ((bid & 1) == 0) {
        int g = bid >> 1;
        if (g >= G1A_BLOCKS) return;
        gemm1_body(g * 32, X, W1, Ws, Xs);
    } else {
        int eb = bid >> 1;                 // < EDGE_BLOCKS
        int is64 = g_is64;
        int base = eb * 1024 + threadIdx.x;
        if (is64) {
            const int2* p = (const int2*)ei;
            #pragma unroll
            for (int i = 0; i < 4; ++i) {
                int e = base + i * 256;
                if (e < N_EDGES) {
                    int d = p[(size_t)N_EDGES + e].x;
                    if ((unsigned)d >= N_NODES) d = 0;
                    atomicAdd(&g_deg[d], 1);
                }
            }
        } else {
            #pragma unroll
            for (int i = 0; i < 4; ++i) {
                int e = base + i * 256;
                if (e < N_EDGES) {
                    int d = ei[(size_t)N_EDGES + e];
                    if ((unsigned)d >= N_NODES) d = 0;
                    atomicAdd(&g_deg[d], 1);
                }
            }
        }
    }
}

// ---------------- fusedB: gemm1 rows [40000, 100000) ⊕ CSR fill --------------
__global__ void __launch_bounds__(256) fusedB_kernel(const float* __restrict__ X,
                                                     const float* __restrict__ W1,
                                                     const int* __restrict__ ei) {
    __shared__ float4 Ws[IN_CH][16];
    __shared__ float  Xs[32][IN_CH];
    int bid = blockIdx.x;
    if ((bid & 1) == 0) {
        int g = (bid >> 1) + G1A_BLOCKS;
        gemm1_body(g * 32, X, W1, Ws, Xs);
    } else {
        int eb = bid >> 1;
        if (eb >= EDGE_BLOCKS) return;
        int is64 = g_is64;
        int base = eb * 1024 + threadIdx.x;
        #pragma unroll
        for (int i = 0; i < 4; ++i) {
            int e = base + i * 256;
            if (e < N_EDGES) {
                int s, d;
                if (is64) {
                    const int2* p = (const int2*)ei;
                    s = p[e].x;
                    d = p[(size_t)N_EDGES + e].x;
                } else {
                    s = ei[e];
                    d = ei[(size_t)N_EDGES + e];
                }
                if ((unsigned)s >= N_NODES) s = 0;
                if ((unsigned)d >= N_NODES) d = 0;
                int pos = atomicAdd(&g_fill[d], 1);   // absolute cursor
                g_csr[pos] = s;
            }
        }
    }
}

// ---------------- scan: shuffle-based, 2 barriers per kernel -----------------
#define SCAN_CHUNK 1024
#define SCAN_NB ((N_NODES + SCAN_CHUNK - 1) / SCAN_CHUNK)   // 98

__global__ void scan_part_kernel() {   // chunk sums + dinv
    __shared__ int wsum[8];
    int b = blockIdx.x, t = threadIdx.x;
    int lane = t & 31, warp = t >> 5;
    int base = b * SCAN_CHUNK;
    int s = 0;
    #pragma unroll
    for (int i = t; i < SCAN_CHUNK; i += 256) {
        int idx = base + i;
        if (idx < N_NODES) {
            int dg = g_deg[idx];
            s += dg;
            g_dinv[idx] = rsqrtf((float)(dg + 1));   // +1 self-loop
        }
    }
    #pragma unroll
    for (int o = 16; o > 0; o >>= 1) s += __shfl_down_sync(0xFFFFFFFFu, s, o);
    if (lane == 0) wsum[warp] = s;
    __syncthreads();
    if (t == 0) {
        int tot = 0;
        #pragma unroll
        for (int w = 0; w < 8; ++w) tot += wsum[w];
        g_partial[b] = tot;
    }
}

__global__ void scan_final_kernel() {  // blockDim = 1024; fill = rowoff cursor
    __shared__ int wsum[32];
    __shared__ int parts[128];
    int b = blockIdx.x, t = threadIdx.x;
    int lane = t & 31, warp = t >> 5;

    // warp 0: scan the 98 partials (4 per lane)
    if (warp == 0) {
        int base = lane * 4;
        int a0 = (base     < SCAN_NB) ? g_partial[base]     : 0;
        int a1 = (base + 1 < SCAN_NB) ? g_partial[base + 1] : 0;
        int a2 = (base + 2 < SCAN_NB) ? g_partial[base + 2] : 0;
        int a3 = (base + 3 < SCAN_NB) ? g_partial[base + 3] : 0;
        int s1 = a0 + a1, s2 = s1 + a2, s3 = s2 + a3;
        int incl = warp_incl_scan(s3, lane);
        int pre = incl - s3;
        parts[base] = pre + a0;
        parts[base + 1] = pre + s1;
        parts[base + 2] = pre + s2;
        parts[base + 3] = pre + s3;
    }

    int idx = b * SCAN_CHUNK + t;
    int v = (idx < N_NODES) ? g_deg[idx] : 0;
    int incl = warp_incl_scan(v, lane);
    if (lane == 31) wsum[warp] = incl;
    __syncthreads();
    if (warp == 0) {
        int s = wsum[lane];
        int si = warp_incl_scan(s, lane);
        wsum[lane] = si - s;       // exclusive
    }
    __syncthreads();
    incl += wsum[warp];

    int off = (b > 0) ? parts[b - 1] : 0;
    if (idx < N_NODES) {
        int ro = off + incl - v;
        g_rowoff[idx] = ro;
        g_fill[idx] = ro;
    }
    if (idx == N_NODES - 1) g_rowoff[N_NODES] = off + incl;
}

// ---------------- fused agg1 + gemm2 (software-pipelined gathers) -------------
#define HS_STRIDE 72
__global__ void __launch_bounds__(256) agg1_gemm2_kernel(const float* __restrict__ b1,
                                                         const float* __restrict__ W2) {
    __shared__ float  Hs[32 * HS_STRIDE];   // 9216 B
    __shared__ float4 Ws[HID][8];           // 8 KB
    int tid = threadIdx.x;

    const float4* W4 = (const float4*)W2;
    #pragma unroll
    for (int i = tid; i < HID * 8; i += 256) Ws[i >> 3][i & 7] = W4[i];

    // ---- Phase A: aggregate layer 1 (quarter-warp per node) ----
    int warp = tid >> 5;
    int lane = tid & 31;
    int sub = lane >> 3;
    int l = lane & 7;
    int nl = warp * 4 + sub;
    int node = blockIdx.x * 32 + nl;

    int beg = g_rowoff[node], end = g_rowoff[node + 1];
    float di = g_dinv[node];
    const uint4* T = (const uint4*)g_t1;

    uint4 sr = T[(size_t)node * 8 + l];
    float2 acc0 = h2f(sr.x), acc1 = h2f(sr.y), acc2 = h2f(sr.z), acc3 = h2f(sr.w);
    acc0.x *= di; acc0.y *= di; acc1.x *= di; acc1.y *= di;
    acc2.x *= di; acc2.y *= di; acc3.x *= di; acc3.y *= di;
    float2 b0 = {0.f, 0.f}, b1a = {0.f, 0.f}, b2a = {0.f, 0.f}, b3 = {0.f, 0.f};

    int j = beg;
    if (j + 4 <= end) {
        // pipelined: csr quad for NEXT iteration prefetched under current gathers
        int n0 = g_csr[j], n1 = g_csr[j + 1], n2 = g_csr[j + 2], n3 = g_csr[j + 3];
        j += 4;
        for (;;) {
            int m0 = n0, m1 = n1, m2 = n2, m3 = n3;
            bool more = (j + 4 <= end);
            // issue current gathers
            float wa = g_dinv[m0], wb = g_dinv[m1], wc = g_dinv[m2], wd = g_dinv[m3];
            uint4 ra = T[(size_t)m0 * 8 + l];
            uint4 rb = T[(size_t)m1 * 8 + l];
            uint4 rc = T[(size_t)m2 * 8 + l];
            uint4 rd = T[(size_t)m3 * 8 + l];
            // prefetch next csr quad while gathers are in flight
            if (more) {
                n0 = g_csr[j]; n1 = g_csr[j + 1]; n2 = g_csr[j + 2]; n3 = g_csr[j + 3];
                j += 4;
            }
            float2 WA = make_float2(wa, wa), WB = make_float2(wb, wb);
            float2 WC = make_float2(wc, wc), WD = make_float2(wd, wd);
            ffma2(acc0, h2f(ra.x), WA); ffma2(acc1, h2f(ra.y), WA);
            ffma2(acc2, h2f(ra.z), WA); ffma2(acc3, h2f(ra.w), WA);
            ffma2(b0,   h2f(rb.x), WB); ffma2(b1a,  h2f(rb.y), WB);
            ffma2(b2a,  h2f(rb.z), WB); ffma2(b3,   h2f(rb.w), WB);
            ffma2(acc0, h2f(rc.x), WC); ffma2(acc1, h2f(rc.y), WC);
            ffma2(acc2, h2f(rc.z), WC); ffma2(acc3, h2f(rc.w), WC);
            ffma2(b0,   h2f(rd.x), WD); ffma2(b1a,  h2f(rd.y), WD);
            ffma2(b2a,  h2f(rd.z), WD); ffma2(b3,   h2f(rd.w), WD);
            if (!more) break;
        }
    }
    for (; j < end; ++j) {
        int s = g_csr[j];
        float w = g_dinv[s];
        uint4 r = T[(size_t)s * 8 + l];
        float2 W_ = make_float2(w, w);
        ffma2(acc0, h2f(r.x), W_); ffma2(acc1, h2f(r.y), W_);
        ffma2(acc2, h2f(r.z), W_); ffma2(acc3, h2f(r.w), W_);
    }
    acc0.x += b0.x;  acc0.y += b0.y;
    acc1.x += b1a.x; acc1.y += b1a.y;
    acc2.x += b2a.x; acc2.y += b2a.y;
    acc3.x += b3.x;  acc3.y += b3.y;

    const float2* B = (const float2*)b1;
    float2 o0 = B[4 * l], o1 = B[4 * l + 1], o2 = B[4 * l + 2], o3 = B[4 * l + 3];
    float2 D = make_float2(di, di);
    ffma2(o0, acc0, D); ffma2(o1, acc1, D); ffma2(o2, acc2, D); ffma2(o3, acc3, D);
    float4* Hrow = (float4*)(Hs + nl * HS_STRIDE);
    Hrow[2 * l]     = make_float4(fmaxf(o0.x, 0.f), fmaxf(o0.y, 0.f),
                                  fmaxf(o1.x, 0.f), fmaxf(o1.y, 0.f));
    Hrow[2 * l + 1] = make_float4(fmaxf(o2.x, 0.f), fmaxf(o2.y, 0.f),
                                  fmaxf(o3.x, 0.f), fmaxf(o3.y, 0.f));
    __syncthreads();

    // ---- Phase B: gemm2, dinv-premult fp16 out ----
    int cg = tid & 7;
    int rs = tid >> 3;
    const float* xp = Hs + rs * HS_STRIDE;
    float2 axy = {0.f, 0.f}, azw = {0.f, 0.f};
    #pragma unroll 8
    for (int k = 0; k < HID; ++k) {
        float4 w = Ws[k][cg];
        float x = xp[k];
        ffma2(axy, make_float2(w.x, w.y), make_float2(x, x));
        ffma2(azw, make_float2(w.z, w.w), make_float2(x, x));
    }
    int row = blockIdx.x * 32 + rs;
    float dr = g_dinv[row];
    g_t2[(size_t)row * 16 + cg * 2]     = __floats2half2_rn(dr * axy.x, dr * axy.y);
    g_t2[(size_t)row * 16 + cg * 2 + 1] = __floats2half2_rn(dr * azw.x, dr * azw.y);
}

// ---------------- aggregate layer 2: half-warp per node, pipelined -----------
__global__ void __launch_bounds__(256) aggregate2_kernel(const float* __restrict__ b2,
                                                         float* __restrict__ out) {
    int gw = (blockIdx.x * blockDim.x + threadIdx.x) >> 5;
    int lane = threadIdx.x & 31;
    int half = lane >> 4;
    int m = lane & 15;
    int node = gw * 2 + half;
    if (node >= N_NODES) return;

    int beg = g_rowoff[node], end = g_rowoff[node + 1];
    float di = g_dinv[node];

    float2 accA = __half22float2(g_t2[(size_t)node * 16 + m]);
    float2 accB = make_float2(0.f, 0.f);

    int j = beg;
    if (j + 4 <= end) {
        int n0 = g_csr[j], n1 = g_csr[j + 1], n2 = g_csr[j + 2], n3 = g_csr[j + 3];
        j += 4;
        for (;;) {
            int m0 = n0, m1 = n1, m2 = n2, m3 = n3;
            bool more = (j + 4 <= end);
            float2 v0 = __half22float2(g_t2[(size_t)m0 * 16 + m]);
            float2 v1 = __half22float2(g_t2[(size_t)m1 * 16 + m]);
            float2 v2 = __half22float2(g_t2[(size_t)m2 * 16 + m]);
            float2 v3 = __half22float2(g_t2[(size_t)m3 * 16 + m]);
            if (more) {
                n0 = g_csr[j]; n1 = g_csr[j + 1]; n2 = g_csr[j + 2]; n3 = g_csr[j + 3];
                j += 4;
            }
            accA.x += v0.x; accA.y += v0.y;
            accB.x += v1.x; accB.y += v1.y;
            accA.x += v2.x; accA.y += v2.y;
            accB.x += v3.x; accB.y += v3.y;
            if (!more) break;
        }
    }
    for (; j < end; ++j) {
        int s = g_csr[j];
        float2 v = __half22float2(g_t2[(size_t)s * 16 + m]);
        accA.x += v.x; accA.y += v.y;
    }
    float2 r;
    r.x = fmaf(di, accA.x + accB.x, b2[2 * m]);
    r.y = fmaf(di, accA.y + accB.y, b2[2 * m + 1]);
    ((float2*)out)[(size_t)node * 16 + m] = r;
}

// ---------------- launch ------------------------------------------------------
extern "C" void kernel_launch(void* const* d_in, const int* in_sizes, int n_in,
                              void* d_out, int out_size) {
    const float* x  = (const float*)d_in[0];
    const int*   ei = (const int*)d_in[1];
    const float* W1 = (const float*)d_in[2];
    const float* b1 = (const float*)d_in[3];
    const float* W2 = (const float*)d_in[4];
    const float* b2 = (const float*)d_in[5];
    float* out = (float*)d_out;

    (void)in_sizes; (void)n_in; (void)out_size;

    init_kernel<<<(N_NODES + 255) / 256, 256>>>(ei);
    fusedA_kernel<<<2 * EDGE_BLOCKS, 256>>>(x, W1, ei);
    scan_part_kernel<<<SCAN_NB, 256>>>();
    scan_final_kernel<<<SCAN_NB, SCAN_CHUNK>>>();
    fusedB_kernel<<<2 * G1B_BLOCKS, 256>>>(x, W1, ei);
    agg1_gemm2_kernel<<<N_NODES / 32, 256>>>(b1, W2);
    aggregate2_kernel<<<(N_NODES / 2 * 32 + 255) / 256, 256>>>(b2, out);
}

// round 17
// speedup vs baseline: 1.7276x; 1.4018x over previous
#include <cuda_runtime.h>
#include <cuda_fp16.h>
#include <stdint.h>

#define N_NODES 100000
#define N_EDGES 1600000
#define IN_CH   128
#define HID     64
#define OUT_CH  32

#define EDGE_BLOCKS 1563           // 1563 * 1024 edges >= N_EDGES
#define G1_BLOCKS   1563           // 1563 * 64 rows >= N_NODES
#define G1A_MMA     625            // rows [0, 40000) in fusedA
#define G1B_MMA     (G1_BLOCKS - G1A_MMA)   // rows [40000, 100032) in fusedB

#define ASTR 136                   // A tile row stride in halves (272B: conflict-free ldmatrix)
#define BSTR 72                    // B tile row stride in halves (144B)

// ---------------- scratch (static device globals; no allocation) -------------
__device__ int     g_is64;
__device__ int     g_deg[N_NODES];
__device__ float   g_dinv[N_NODES];
__device__ int     g_rowoff[N_NODES + 1];
__device__ int     g_fill[N_NODES];          // running CSR cursor (init = rowoff)
__device__ int     g_csr[N_EDGES];
__device__ int     g_partial[128];
__device__ __half2 g_t1[(size_t)N_NODES * 32];   // m1 in fp16 (64 ch)
__device__ __half2 g_t2[(size_t)N_NODES * 16];   // dinv * m2 in fp16 (32 ch)

// ---------------- packed fp32x2 FMA (Blackwell FFMA2) ------------------------
__device__ __forceinline__ void ffma2(float2& c, float2 a, float2 b) {
    unsigned long long A = *reinterpret_cast<unsigned long long*>(&a);
    unsigned long long B = *reinterpret_cast<unsigned long long*>(&b);
    unsigned long long C = *reinterpret_cast<unsigned long long*>(&c);
    asm("fma.rn.f32x2 %0, %1, %2, %3;" : "=l"(C) : "l"(A), "l"(B), "l"(C));
    c = *reinterpret_cast<float2*>(&C);
}
__device__ __forceinline__ float2 h2f(unsigned u) {
    return __half22float2(*(__half2*)&u);
}
__device__ __forceinline__ int warp_incl_scan(int x, int lane) {
    #pragma unroll
    for (int o = 1; o < 32; o <<= 1) {
        int t = __shfl_up_sync(0xFFFFFFFFu, x, o);
        if (lane >= o) x += t;
    }
    return x;
}

// ---------------- tensor-core primitives -------------------------------------
__device__ __forceinline__ void ldsm_x4(unsigned* r, unsigned addr) {
    asm volatile("ldmatrix.sync.aligned.m8n8.x4.shared.b16 {%0,%1,%2,%3},[%4];"
                 : "=r"(r[0]), "=r"(r[1]), "=r"(r[2]), "=r"(r[3]) : "r"(addr));
}
__device__ __forceinline__ void ldsm_x4_t(unsigned* r, unsigned addr) {
    asm volatile("ldmatrix.sync.aligned.m8n8.x4.trans.shared.b16 {%0,%1,%2,%3},[%4];"
                 : "=r"(r[0]), "=r"(r[1]), "=r"(r[2]), "=r"(r[3]) : "r"(addr));
}
__device__ __forceinline__ void mma16816(float* d, const unsigned* a, const unsigned* b) {
    asm volatile("mma.sync.aligned.m16n8k16.row.col.f32.f16.f16.f32 "
                 "{%0,%1,%2,%3},{%4,%5,%6,%7},{%8,%9},{%0,%1,%2,%3};"
                 : "+f"(d[0]), "+f"(d[1]), "+f"(d[2]), "+f"(d[3])
                 : "r"(a[0]), "r"(a[1]), "r"(a[2]), "r"(a[3]), "r"(b[0]), "r"(b[1]));
}

// ---------------- init: zero deg + dtype sniff --------------------------------
__global__ void init_kernel(const int* __restrict__ ei32) {
    int i = blockIdx.x * blockDim.x + threadIdx.x;
    if (i < N_NODES) g_deg[i] = 0;
    if (blockIdx.x == 0 && threadIdx.x < 32) {
        int lane = threadIdx.x;
        int bad = 0;
        for (int e = lane; e < 256; e += 32)
            if (ei32[2 * e + 1] != 0) bad = 1;
        unsigned m = __ballot_sync(0xFFFFFFFFu, bad);
        if (lane == 0) g_is64 = (m == 0);
    }
}

// ---------------- GEMM1 via HMMA: 64 rows x 64 cols per block -----------------
__device__ __forceinline__ void gemm1_mma_body(int row0,
                                               const float* __restrict__ X,
                                               const float* __restrict__ W,
                                               __half* As, __half* Bs) {
    int tid = threadIdx.x;

    // load + convert W1 [128 x 64] fp32 -> fp16 SMEM (BSTR stride)
    const float4* W4 = (const float4*)W;
    #pragma unroll
    for (int i = tid; i < IN_CH * HID / 4; i += 256) {
        int row = i >> 4, c4 = i & 15;
        float4 v = W4[i];
        __half2* p = (__half2*)(Bs + row * BSTR + c4 * 4);
        p[0] = __floats2half2_rn(v.x, v.y);
        p[1] = __floats2half2_rn(v.z, v.w);
    }
    // load + convert X [64 x 128] fp32 -> fp16 SMEM (ASTR stride)
    const float4* Xg = (const float4*)(X + (size_t)row0 * IN_CH);
    #pragma unroll
    for (int i = tid; i < 64 * IN_CH / 4; i += 256) {
        int r = i >> 5, c4 = i & 31;
        float4 v = (row0 + r < N_NODES) ? Xg[i] : make_float4(0.f, 0.f, 0.f, 0.f);
        __half2* p = (__half2*)(As + r * ASTR + c4 * 4);
        p[0] = __floats2half2_rn(v.x, v.y);
        p[1] = __floats2half2_rn(v.z, v.w);
    }
    __syncthreads();

    int warp = tid >> 5, lane = tid & 31;
    int wm = warp & 3;            // m tile: rows wm*16
    int wn = warp >> 2;           // n tile: cols wn*32

    float acc[4][4] = {};
    unsigned aBase = (unsigned)__cvta_generic_to_shared(As);
    unsigned bBase = (unsigned)__cvta_generic_to_shared(Bs);
    int lr = lane & 15, lh = lane >> 4;

    #pragma unroll
    for (int kc = 0; kc < 8; ++kc) {
        unsigned a[4];
        ldsm_x4(a, aBase + 2u * ((wm * 16 + lr) * ASTR + kc * 16 + lh * 8));
        unsigned b0[4], b1[4];
        ldsm_x4_t(b0, bBase + 2u * ((kc * 16 + lr) * BSTR + wn * 32 + lh * 8));
        ldsm_x4_t(b1, bBase + 2u * ((kc * 16 + lr) * BSTR + wn * 32 + 16 + lh * 8));
        mma16816(acc[0], a, b0);       // n8 group 0: regs {b0[0], b0[1]}
        mma16816(acc[1], a, b0 + 2);   // n8 group 1
        mma16816(acc[2], a, b1);       // n8 group 2
        mma16816(acc[3], a, b1 + 2);   // n8 group 3
    }

    // epilogue: fp16 into g_t1
    int g = lane >> 2, t = lane & 3;
    int node0 = row0 + wm * 16 + g;
    int node1 = node0 + 8;
    #pragma unroll
    for (int f = 0; f < 4; ++f) {
        int hidx = wn * 16 + f * 4 + t;
        if (node0 < N_NODES)
            g_t1[(size_t)node0 * 32 + hidx] = __floats2half2_rn(acc[f][0], acc[f][1]);
        if (node1 < N_NODES)
            g_t1[(size_t)node1 * 32 + hidx] = __floats2half2_rn(acc[f][2], acc[f][3]);
    }
}

// ---------------- fusedA: gemm1 rows [0, 40000) ⊕ degree count ---------------
__global__ void __launch_bounds__(256) fusedA_kernel(const float* __restrict__ X,
                                                     const float* __restrict__ W1,
                                                     const int* __restrict__ ei) {
    __shared__ __half As[64 * ASTR];
    __shared__ __half Bs[IN_CH * BSTR];
    int bid = blockIdx.x;
    if ((bid & 1) == 0) {
        int g = bid >> 1;
        if (g >= G1A_MMA) return;
        gemm1_mma_body(g * 64, X, W1, As, Bs);
    } else {
        int eb = bid >> 1;                 // < EDGE_BLOCKS
        int is64 = g_is64;
        int base = eb * 1024 + threadIdx.x;
        if (is64) {
            const int2* p = (const int2*)ei;
            #pragma unroll
            for (int i = 0; i < 4; ++i) {
                int e = base + i * 256;
                if (e < N_EDGES) {
                    int d = p[(size_t)N_EDGES + e].x;
                    if ((unsigned)d >= N_NODES) d = 0;
                    atomicAdd(&g_deg[d], 1);
                }
            }
        } else {
            #pragma unroll
            for (int i = 0; i < 4; ++i) {
                int e = base + i * 256;
                if (e < N_EDGES) {
                    int d = ei[(size_t)N_EDGES + e];
                    if ((unsigned)d >= N_NODES) d = 0;
                    atomicAdd(&g_deg[d], 1);
                }
            }
        }
    }
}

// ---------------- fusedB: gemm1 rows [40000, 100000) ⊕ CSR fill --------------
__global__ void __launch_bounds__(256) fusedB_kernel(const float* __restrict__ X,
                                                     const float* __restrict__ W1,
                                                     const int* __restrict__ ei) {
    __shared__ __half As[64 * ASTR];
    __shared__ __half Bs[IN_CH * BSTR];
    int bid = blockIdx.x;
    if ((bid & 1) == 0) {
        int g = bid >> 1;
        if (g >= G1B_MMA) return;
        gemm1_mma_body((g + G1A_MMA) * 64, X, W1, As, Bs);
    } else {
        int eb = bid >> 1;
        if (eb >= EDGE_BLOCKS) return;
        int is64 = g_is64;
        int base = eb * 1024 + threadIdx.x;
        #pragma unroll
        for (int i = 0; i < 4; ++i) {
            int e = base + i * 256;
            if (e < N_EDGES) {
                int s, d;
                if (is64) {
                    const int2* p = (const int2*)ei;
                    s = p[e].x;
                    d = p[(size_t)N_EDGES + e].x;
                } else {
                    s = ei[e];
                    d = ei[(size_t)N_EDGES + e];
                }
                if ((unsigned)s >= N_NODES) s = 0;
                if ((unsigned)d >= N_NODES) d = 0;
                int pos = atomicAdd(&g_fill[d], 1);   // absolute cursor
                g_csr[pos] = s;
            }
        }
    }
}

// ---------------- scan: shuffle-based ----------------------------------------
#define SCAN_CHUNK 1024
#define SCAN_NB ((N_NODES + SCAN_CHUNK - 1) / SCAN_CHUNK)   // 98

__global__ void scan_part_kernel() {   // chunk sums + dinv
    __shared__ int wsum[8];
    int b = blockIdx.x, t = threadIdx.x;
    int lane = t & 31, warp = t >> 5;
    int base = b * SCAN_CHUNK;
    int s = 0;
    #pragma unroll
    for (int i = t; i < SCAN_CHUNK; i += 256) {
        int idx = base + i;
        if (idx < N_NODES) {
            int dg = g_deg[idx];
            s += dg;
            g_dinv[idx] = rsqrtf((float)(dg + 1));   // +1 self-loop
        }
    }
    #pragma unroll
    for (int o = 16; o > 0; o >>= 1) s += __shfl_down_sync(0xFFFFFFFFu, s, o);
    if (lane == 0) wsum[warp] = s;
    __syncthreads();
    if (t == 0) {
        int tot = 0;
        #pragma unroll
        for (int w = 0; w < 8; ++w) tot += wsum[w];
        g_partial[b] = tot;
    }
}

__global__ void scan_final_kernel() {  // blockDim = 1024; fill = rowoff cursor
    __shared__ int wsum[32];
    __shared__ int parts[128];
    int b = blockIdx.x, t = threadIdx.x;
    int lane = t & 31, warp = t >> 5;

    if (warp == 0) {
        int base = lane * 4;
        int a0 = (base     < SCAN_NB) ? g_partial[base]     : 0;
        int a1 = (base + 1 < SCAN_NB) ? g_partial[base + 1] : 0;
        int a2 = (base + 2 < SCAN_NB) ? g_partial[base + 2] : 0;
        int a3 = (base + 3 < SCAN_NB) ? g_partial[base + 3] : 0;
        int s1 = a0 + a1, s2 = s1 + a2, s3 = s2 + a3;
        int incl = warp_incl_scan(s3, lane);
        int pre = incl - s3;
        parts[base] = pre + a0;
        parts[base + 1] = pre + s1;
        parts[base + 2] = pre + s2;
        parts[base + 3] = pre + s3;
    }

    int idx = b * SCAN_CHUNK + t;
    int v = (idx < N_NODES) ? g_deg[idx] : 0;
    int incl = warp_incl_scan(v, lane);
    if (lane == 31) wsum[warp] = incl;
    __syncthreads();
    if (warp == 0) {
        int s = wsum[lane];
        int si = warp_incl_scan(s, lane);
        wsum[lane] = si - s;
    }
    __syncthreads();
    incl += wsum[warp];

    int off = (b > 0) ? parts[b - 1] : 0;
    if (idx < N_NODES) {
        int ro = off + incl - v;
        g_rowoff[idx] = ro;
        g_fill[idx] = ro;
    }
    if (idx == N_NODES - 1) g_rowoff[N_NODES] = off + incl;
}

// ---------------- fused agg1 + gemm2 (software-pipelined gathers) -------------
#define HS_STRIDE 72
__global__ void __launch_bounds__(256) agg1_gemm2_kernel(const float* __restrict__ b1,
                                                         const float* __restrict__ W2) {
    __shared__ float  Hs[32 * HS_STRIDE];   // 9216 B
    __shared__ float4 Ws[HID][8];           // 8 KB
    int tid = threadIdx.x;

    const float4* W4 = (const float4*)W2;
    #pragma unroll
    for (int i = tid; i < HID * 8; i += 256) Ws[i >> 3][i & 7] = W4[i];

    // ---- Phase A: aggregate layer 1 (quarter-warp per node) ----
    int warp = tid >> 5;
    int lane = tid & 31;
    int sub = lane >> 3;
    int l = lane & 7;
    int nl = warp * 4 + sub;
    int node = blockIdx.x * 32 + nl;

    int beg = g_rowoff[node], end = g_rowoff[node + 1];
    float di = g_dinv[node];
    const uint4* T = (const uint4*)g_t1;

    uint4 sr = T[(size_t)node * 8 + l];
    float2 acc0 = h2f(sr.x), acc1 = h2f(sr.y), acc2 = h2f(sr.z), acc3 = h2f(sr.w);
    acc0.x *= di; acc0.y *= di; acc1.x *= di; acc1.y *= di;
    acc2.x *= di; acc2.y *= di; acc3.x *= di; acc3.y *= di;
    float2 b0 = {0.f, 0.f}, b1a = {0.f, 0.f}, b2a = {0.f, 0.f}, b3 = {0.f, 0.f};

    int j = beg;
    if (j + 4 <= end) {
        int n0 = g_csr[j], n1 = g_csr[j + 1], n2 = g_csr[j + 2], n3 = g_csr[j + 3];
        j += 4;
        for (;;) {
            int m0 = n0, m1 = n1, m2 = n2, m3 = n3;
            bool more = (j + 4 <= end);
            float wa = g_dinv[m0], wb = g_dinv[m1], wc = g_dinv[m2], wd = g_dinv[m3];
            uint4 ra = T[(size_t)m0 * 8 + l];
            uint4 rb = T[(size_t)m1 * 8 + l];
            uint4 rc = T[(size_t)m2 * 8 + l];
            uint4 rd = T[(size_t)m3 * 8 + l];
            if (more) {
                n0 = g_csr[j]; n1 = g_csr[j + 1]; n2 = g_csr[j + 2]; n3 = g_csr[j + 3];
                j += 4;
            }
            float2 WA = make_float2(wa, wa), WB = make_float2(wb, wb);
            float2 WC = make_float2(wc, wc), WD = make_float2(wd, wd);
            ffma2(acc0, h2f(ra.x), WA); ffma2(acc1, h2f(ra.y), WA);
            ffma2(acc2, h2f(ra.z), WA); ffma2(acc3, h2f(ra.w), WA);
            ffma2(b0,   h2f(rb.x), WB); ffma2(b1a,  h2f(rb.y), WB);
            ffma2(b2a,  h2f(rb.z), WB); ffma2(b3,   h2f(rb.w), WB);
            ffma2(acc0, h2f(rc.x), WC); ffma2(acc1, h2f(rc.y), WC);
            ffma2(acc2, h2f(rc.z), WC); ffma2(acc3, h2f(rc.w), WC);
            ffma2(b0,   h2f(rd.x), WD); ffma2(b1a,  h2f(rd.y), WD);
            ffma2(b2a,  h2f(rd.z), WD); ffma2(b3,   h2f(rd.w), WD);
            if (!more) break;
        }
    }
    for (; j < end; ++j) {
        int s = g_csr[j];
        float w = g_dinv[s];
        uint4 r = T[(size_t)s * 8 + l];
        float2 W_ = make_float2(w, w);
        ffma2(acc0, h2f(r.x), W_); ffma2(acc1, h2f(r.y), W_);
        ffma2(acc2, h2f(r.z), W_); ffma2(acc3, h2f(r.w), W_);
    }
    acc0.x += b0.x;  acc0.y += b0.y;
    acc1.x += b1a.x; acc1.y += b1a.y;
    acc2.x += b2a.x; acc2.y += b2a.y;
    acc3.x += b3.x;  acc3.y += b3.y;

    const float2* B = (const float2*)b1;
    float2 o0 = B[4 * l], o1 = B[4 * l + 1], o2 = B[4 * l + 2], o3 = B[4 * l + 3];
    float2 D = make_float2(di, di);
    ffma2(o0, acc0, D); ffma2(o1, acc1, D); ffma2(o2, acc2, D); ffma2(o3, acc3, D);
    float4* Hrow = (float4*)(Hs + nl * HS_STRIDE);
    Hrow[2 * l]     = make_float4(fmaxf(o0.x, 0.f), fmaxf(o0.y, 0.f),
                                  fmaxf(o1.x, 0.f), fmaxf(o1.y, 0.f));
    Hrow[2 * l + 1] = make_float4(fmaxf(o2.x, 0.f), fmaxf(o2.y, 0.f),
                                  fmaxf(o3.x, 0.f), fmaxf(o3.y, 0.f));
    __syncthreads();

    // ---- Phase B: gemm2, dinv-premult fp16 out ----
    int cg = tid & 7;
    int rs = tid >> 3;
    const float* xp = Hs + rs * HS_STRIDE;
    float2 axy = {0.f, 0.f}, azw = {0.f, 0.f};
    #pragma unroll 8
    for (int k = 0; k < HID; ++k) {
        float4 w = Ws[k][cg];
        float x = xp[k];
        ffma2(axy, make_float2(w.x, w.y), make_float2(x, x));
        ffma2(azw, make_float2(w.z, w.w), make_float2(x, x));
    }
    int row = blockIdx.x * 32 + rs;
    float dr = g_dinv[row];
    g_t2[(size_t)row * 16 + cg * 2]     = __floats2half2_rn(dr * axy.x, dr * axy.y);
    g_t2[(size_t)row * 16 + cg * 2 + 1] = __floats2half2_rn(dr * azw.x, dr * azw.y);
}

// ---------------- aggregate layer 2: half-warp per node, pipelined -----------
__global__ void __launch_bounds__(256) aggregate2_kernel(const float* __restrict__ b2,
                                                         float* __restrict__ out) {
    int gw = (blockIdx.x * blockDim.x + threadIdx.x) >> 5;
    int lane = threadIdx.x & 31;
    int half = lane >> 4;
    int m = lane & 15;
    int node = gw * 2 + half;
    if (node >= N_NODES) return;

    int beg = g_rowoff[node], end = g_rowoff[node + 1];
    float di = g_dinv[node];

    float2 accA = __half22float2(g_t2[(size_t)node * 16 + m]);
    float2 accB = make_float2(0.f, 0.f);

    int j = beg;
    if (j + 4 <= end) {
        int n0 = g_csr[j], n1 = g_csr[j + 1], n2 = g_csr[j + 2], n3 = g_csr[j + 3];
        j += 4;
        for (;;) {
            int m0 = n0, m1 = n1, m2 = n2, m3 = n3;
            bool more = (j + 4 <= end);
            float2 v0 = __half22float2(g_t2[(size_t)m0 * 16 + m]);
            float2 v1 = __half22float2(g_t2[(size_t)m1 * 16 + m]);
            float2 v2 = __half22float2(g_t2[(size_t)m2 * 16 + m]);
            float2 v3 = __half22float2(g_t2[(size_t)m3 * 16 + m]);
            if (more) {
                n0 = g_csr[j]; n1 = g_csr[j + 1]; n2 = g_csr[j + 2]; n3 = g_csr[j + 3];
                j += 4;
            }
            accA.x += v0.x; accA.y += v0.y;
            accB.x += v1.x; accB.y += v1.y;
            accA.x += v2.x; accA.y += v2.y;
            accB.x += v3.x; accB.y += v3.y;
            if (!more) break;
        }
    }
    for (; j < end; ++j) {
        int s = g_csr[j];
        float2 v = __half22float2(g_t2[(size_t)s * 16 + m]);
        accA.x += v.x; accA.y += v.y;
    }
    float2 r;
    r.x = fmaf(di, accA.x + accB.x, b2[2 * m]);
    r.y = fmaf(di, accA.y + accB.y, b2[2 * m + 1]);
    ((float2*)out)[(size_t)node * 16 + m] = r;
}

// ---------------- launch ------------------------------------------------------
extern "C" void kernel_launch(void* const* d_in, const int* in_sizes, int n_in,
                              void* d_out, int out_size) {
    const float* x  = (const float*)d_in[0];
    const int*   ei = (const int*)d_in[1];
    const float* W1 = (const float*)d_in[2];
    const float* b1 = (const float*)d_in[3];
    const float* W2 = (const float*)d_in[4];
    const float* b2 = (const float*)d_in[5];
    float* out = (float*)d_out;

    (void)in_sizes; (void)n_in; (void)out_size;

    init_kernel<<<(N_NODES + 255) / 256, 256>>>(ei);
    fusedA_kernel<<<2 * EDGE_BLOCKS, 256>>>(x, W1, ei);
    scan_part_kernel<<<SCAN_NB, 256>>>();
    scan_final_kernel<<<SCAN_NB, SCAN_CHUNK>>>();
    fusedB_kernel<<<2 * EDGE_BLOCKS, 256>>>(x, W1, ei);
    agg1_gemm2_kernel<<<N_NODES / 32, 256>>>(b1, W2);
    aggregate2_kernel<<<(N_NODES / 2 * 32 + 255) / 256, 256>>>(b2, out);
}